// round 1
// baseline (speedup 1.0000x reference)
#include <cuda_runtime.h>
#include <math.h>

#define Bb 8
#define Tt 512
#define Cc 256
#define Kk 4
constexpr int BT    = Bb * Tt;     // 4096
constexpr int NPROJ = 1792;        // [q|k|qs|v|mq|mk|mv] each 256 cols
constexpr float NEGV = -1e22f;

// -------- scratch (static device allocations; no cudaMalloc anywhere) -------
__device__ float g_Wall[NPROJ * Cc];        // packed weights (1792 x 256)
__device__ int   g_idx [BT * Kk];           // neighbor indices
__device__ float g_proj[(long)BT * NPROJ];  // all projections
__device__ float g_A2  [(long)Bb * Tt * 512];  // [qs | kn_sum]
__device__ float g_B2  [(long)Bb * Tt * 512];  // [qs | k]
__device__ float g_Gq  [(long)Bb * Tt * Tt];   // q-gram per batch
__device__ float g_L   [(long)Bb * Tt * Tt];   // graph-attn logits -> probs
__device__ float g_D   [(long)Bb * Tt * Tt];   // MHA logits -> probs

// ---------------------------------------------------------------- pack weights
__global__ void pack_w(const float* __restrict__ Wq, const float* __restrict__ Wk,
                       const float* __restrict__ Wqs, const float* __restrict__ Wv,
                       const float* __restrict__ Wqkv, float* __restrict__ Wall) {
    int i = blockIdx.x * blockDim.x + threadIdx.x;
    if (i >= NPROJ * Cc) return;
    int row = i / Cc, col = i % Cc;
    float v;
    if      (row <  256) v = Wq  [ row         * Cc + col];
    else if (row <  512) v = Wk  [(row -  256) * Cc + col];
    else if (row <  768) v = Wqs [(row -  512) * Cc + col];
    else if (row < 1024) v = Wv  [(row -  768) * Cc + col];
    else                 v = Wqkv[(row - 1024) * Cc + col];
    Wall[i] = v;
}

// --------------------------------------------------- recover idx from one-hot
__global__ void extract_idx(const float* __restrict__ inxs, int* __restrict__ idx) {
    int i = blockIdx.x * blockDim.x + threadIdx.x;   // over BT*K
    if (i >= BT * Kk) return;
    const float4* p = (const float4*)(inxs + (long)i * Tt);
    int found = 0;
    for (int j = 0; j < Tt / 4; j++) {
        float4 v = p[j];
        if (v.x > 0.5f) found = 4 * j;
        if (v.y > 0.5f) found = 4 * j + 1;
        if (v.z > 0.5f) found = 4 * j + 2;
        if (v.w > 0.5f) found = 4 * j + 3;
    }
    idx[i] = found;
}

// ------------------------------------------------------------- generic GEMMs
// NT: C[m,n] = alpha * sum_k A[m,k]*B[n,k]   (both row-major, K contiguous)
// flags: 1 = add adj mask (0 -> NEG), 2 = accumulate into C
__global__ void gemm_nt(const float* __restrict__ A, const float* __restrict__ Bm,
                        float* __restrict__ Cm, int Kdim,
                        int lda, int ldb, int ldc,
                        long sA, long sB, long sC, float alpha,
                        const float* __restrict__ mask, long sMask, int ldm,
                        int flags) {
    constexpr int BM = 64, BN = 64, BK = 16;
    A  += (long)blockIdx.z * sA;
    Bm += (long)blockIdx.z * sB;
    Cm += (long)blockIdx.z * sC;
    __shared__ float As[BK][BM + 1];
    __shared__ float Bs[BK][BN + 1];
    int tid = threadIdx.x;
    int tx = tid & 15, ty = tid >> 4;
    int m0 = blockIdx.y * BM, n0 = blockIdx.x * BN;
    int lr = tid >> 2, lc = (tid & 3) * 4;
    float acc[4][4] = {};
    for (int k0 = 0; k0 < Kdim; k0 += BK) {
        float4 av = *(const float4*)(A  + (long)(m0 + lr) * lda + k0 + lc);
        float4 bv = *(const float4*)(Bm + (long)(n0 + lr) * ldb + k0 + lc);
        __syncthreads();
        As[lc + 0][lr] = av.x; As[lc + 1][lr] = av.y;
        As[lc + 2][lr] = av.z; As[lc + 3][lr] = av.w;
        Bs[lc + 0][lr] = bv.x; Bs[lc + 1][lr] = bv.y;
        Bs[lc + 2][lr] = bv.z; Bs[lc + 3][lr] = bv.w;
        __syncthreads();
#pragma unroll
        for (int kk = 0; kk < BK; kk++) {
            float a[4], b[4];
#pragma unroll
            for (int i = 0; i < 4; i++) a[i] = As[kk][ty * 4 + i];
#pragma unroll
            for (int j = 0; j < 4; j++) b[j] = Bs[kk][tx * 4 + j];
#pragma unroll
            for (int i = 0; i < 4; i++)
#pragma unroll
                for (int j = 0; j < 4; j++) acc[i][j] += a[i] * b[j];
        }
    }
    int m = m0 + ty * 4, n = n0 + tx * 4;
#pragma unroll
    for (int i = 0; i < 4; i++)
#pragma unroll
        for (int j = 0; j < 4; j++) {
            float v = acc[i][j] * alpha;
            if (flags & 1) {
                float a = mask[(long)blockIdx.z * sMask + (long)(m + i) * ldm + (n + j)];
                if (a == 0.0f) v += NEGV;
            }
            long off = (long)(m + i) * ldc + (n + j);
            if (flags & 2) Cm[off] += v; else Cm[off] = v;
        }
}

// NN: C[m,n] = alpha * sum_k A[m,k]*B[k,n]
__global__ void gemm_nn(const float* __restrict__ A, const float* __restrict__ Bm,
                        float* __restrict__ Cm, int Kdim,
                        int lda, int ldb, int ldc,
                        long sA, long sB, long sC, float alpha, int flags) {
    constexpr int BM = 64, BN = 64, BK = 16;
    A  += (long)blockIdx.z * sA;
    Bm += (long)blockIdx.z * sB;
    Cm += (long)blockIdx.z * sC;
    __shared__ float As[BK][BM + 1];
    __shared__ float Bs[BK][BN + 1];
    int tid = threadIdx.x;
    int tx = tid & 15, ty = tid >> 4;
    int m0 = blockIdx.y * BM, n0 = blockIdx.x * BN;
    int ar = tid >> 2, ac = (tid & 3) * 4;   // A loader: 64 rows x 16 cols
    int br = tid >> 4, bc = (tid & 15) * 4;  // B loader: 16 rows x 64 cols
    float acc[4][4] = {};
    for (int k0 = 0; k0 < Kdim; k0 += BK) {
        float4 av = *(const float4*)(A  + (long)(m0 + ar) * lda + k0 + ac);
        float4 bv = *(const float4*)(Bm + (long)(k0 + br) * ldb + n0 + bc);
        __syncthreads();
        As[ac + 0][ar] = av.x; As[ac + 1][ar] = av.y;
        As[ac + 2][ar] = av.z; As[ac + 3][ar] = av.w;
        Bs[br][bc + 0] = bv.x; Bs[br][bc + 1] = bv.y;
        Bs[br][bc + 2] = bv.z; Bs[br][bc + 3] = bv.w;
        __syncthreads();
#pragma unroll
        for (int kk = 0; kk < BK; kk++) {
            float a[4], b[4];
#pragma unroll
            for (int i = 0; i < 4; i++) a[i] = As[kk][ty * 4 + i];
#pragma unroll
            for (int j = 0; j < 4; j++) b[j] = Bs[kk][tx * 4 + j];
#pragma unroll
            for (int i = 0; i < 4; i++)
#pragma unroll
                for (int j = 0; j < 4; j++) acc[i][j] += a[i] * b[j];
        }
    }
    int m = m0 + ty * 4, n = n0 + tx * 4;
#pragma unroll
    for (int i = 0; i < 4; i++)
#pragma unroll
        for (int j = 0; j < 4; j++) {
            float v = acc[i][j] * alpha;
            long off = (long)(m + i) * ldc + (n + j);
            if (flags & 2) Cm[off] += v; else Cm[off] = v;
        }
}

// --------------------------------------------- l2-normalize q, k, qs segments
__global__ void normalize_rows(float* __restrict__ proj) {
    long row = blockIdx.x;
    int tid = threadIdx.x;
    __shared__ float red[8];
    __shared__ float bcast;
    for (int seg = 0; seg < 3; seg++) {
        long o = row * NPROJ + seg * 256 + tid;
        float v = proj[o];
        float ss = v * v;
#pragma unroll
        for (int d = 16; d > 0; d >>= 1) ss += __shfl_xor_sync(0xffffffffu, ss, d);
        if ((tid & 31) == 0) red[tid >> 5] = ss;
        __syncthreads();
        if (tid == 0) {
            float s = 0.f;
            for (int i = 0; i < 8; i++) s += red[i];
            bcast = 1.0f / fmaxf(sqrtf(s), 1e-12f);
        }
        __syncthreads();
        proj[o] = v * bcast;
        __syncthreads();
    }
}

// -------------------------------------- build [qs|kn_sum] and [qs|k] matrices
__global__ void build_ab(const float* __restrict__ proj, const int* __restrict__ idx,
                         float* __restrict__ A2, float* __restrict__ B2,
                         const float* __restrict__ ns_w) {
    int row = blockIdx.x;            // b*T + x
    int c = threadIdx.x;             // 0..255
    int b = row >> 9;
    long pbase = (long)row * NPROJ;
    float qs = proj[pbase + 512 + c];
    float kv = proj[pbase + 256 + c];
    long o = (long)row * 512;
    B2[o + c] = qs;
    B2[o + 256 + c] = kv;
    A2[o + c] = qs;
    float s = 0.f;
#pragma unroll
    for (int n = 0; n < Kk; n++) {
        int t = idx[row * Kk + n];
        s += ns_w[n] * proj[((long)(b * Tt + t)) * NPROJ + 256 + c];
    }
    A2[o + 256 + c] = s;
}

// -------------------------------------- sim_nn: gather/max from Gq, add to L
__global__ void add_simnn(const float* __restrict__ Gq, const int* __restrict__ idx,
                          float* __restrict__ L, const float* __restrict__ nn_w) {
    int i = blockIdx.x, b = blockIdx.y;
    int tid = threadIdx.x;
    __shared__ float srow[4][Tt];
    __shared__ int   sjdx[Tt * Kk];
    __shared__ float w[4];
    if (tid < 4) w[tid] = nn_w[tid];
    for (int j = tid; j < Tt * Kk; j += 256) sjdx[j] = idx[b * Tt * Kk + j];
#pragma unroll
    for (int x = 0; x < 4; x++) {
        int rx = idx[(b * Tt + i) * Kk + x];
        for (int c = tid; c < Tt; c += 256)
            srow[x][c] = Gq[((long)b * Tt + rx) * Tt + c];
    }
    __syncthreads();
    for (int j = tid; j < Tt; j += 256) {
        float acc = 0.f;
#pragma unroll
        for (int x = 0; x < 4; x++) {
            float m = -3.4e38f;
#pragma unroll
            for (int y = 0; y < 4; y++)
                m = fmaxf(m, srow[x][sjdx[j * Kk + y]]);
            acc += w[x] * m;
        }
        L[((long)b * Tt + i) * Tt + j] += acc;
    }
}

// ----------------------------------------------------- row softmax (L and D)
__global__ void softmax_rows(float* __restrict__ L, float* __restrict__ D) {
    float* p = (blockIdx.y == 0 ? L : D) + (long)blockIdx.x * Tt;
    int tid = threadIdx.x;
    __shared__ float red[8];
    __shared__ float bcast;
    float2 v = ((float2*)p)[tid];
    float m = fmaxf(v.x, v.y);
#pragma unroll
    for (int d = 16; d > 0; d >>= 1) m = fmaxf(m, __shfl_xor_sync(0xffffffffu, m, d));
    if ((tid & 31) == 0) red[tid >> 5] = m;
    __syncthreads();
    if (tid == 0) {
        float mm = red[0];
        for (int i = 1; i < 8; i++) mm = fmaxf(mm, red[i]);
        bcast = mm;
    }
    __syncthreads();
    float mm = bcast;
    float e0 = __expf(v.x - mm), e1 = __expf(v.y - mm);
    float s = e0 + e1;
#pragma unroll
    for (int d = 16; d > 0; d >>= 1) s += __shfl_xor_sync(0xffffffffu, s, d);
    if ((tid & 31) == 0) red[tid >> 5] = s;
    __syncthreads();
    if (tid == 0) {
        float ss = 0.f;
        for (int i = 0; i < 8; i++) ss += red[i];
        bcast = 1.0f / ss;
    }
    __syncthreads();
    float inv = bcast;
    ((float2*)p)[tid] = make_float2(e0 * inv, e1 * inv);
}

// ---------------------------------------------------------------------- host
extern "C" void kernel_launch(void* const* d_in, const int* in_sizes, int n_in,
                              void* d_out, int out_size) {
    const float* x    = (const float*)d_in[0];
    const float* adj  = (const float*)d_in[1];
    const float* inxs = (const float*)d_in[2];
    const float* Wq   = (const float*)d_in[3];
    const float* Wk   = (const float*)d_in[4];
    const float* Wqs  = (const float*)d_in[5];
    const float* Wv   = (const float*)d_in[6];
    const float* nn_w = (const float*)d_in[7];
    const float* ns_w = (const float*)d_in[8];
    const float* Wqkv = (const float*)d_in[9];
    float* out = (float*)d_out;

    float *pWall, *pProj, *pA2, *pB2, *pGq, *pL, *pD; int* pIdx;
    cudaGetSymbolAddress((void**)&pWall, g_Wall);
    cudaGetSymbolAddress((void**)&pIdx,  g_idx);
    cudaGetSymbolAddress((void**)&pProj, g_proj);
    cudaGetSymbolAddress((void**)&pA2,   g_A2);
    cudaGetSymbolAddress((void**)&pB2,   g_B2);
    cudaGetSymbolAddress((void**)&pGq,   g_Gq);
    cudaGetSymbolAddress((void**)&pL,    g_L);
    cudaGetSymbolAddress((void**)&pD,    g_D);

    const long sTT = (long)Tt * Tt;       // per-batch TxT
    const long sTP = (long)Tt * NPROJ;    // per-batch proj rows
    const long sT5 = (long)Tt * 512;      // per-batch A2/B2
    const long sTC = (long)Tt * Cc;       // per-batch output

    pack_w<<<(NPROJ * Cc + 255) / 256, 256>>>(Wq, Wk, Wqs, Wv, Wqkv, pWall);
    extract_idx<<<(BT * Kk + 127) / 128, 128>>>(inxs, pIdx);

    // proj = x @ Wall^T : (4096 x 1792), K=256
    gemm_nt<<<dim3(NPROJ / 64, BT / 64, 1), 256>>>(
        x, pWall, pProj, Cc, Cc, Cc, NPROJ, 0, 0, 0, 1.0f, nullptr, 0, 0, 0);

    normalize_rows<<<BT, 256>>>(pProj);
    build_ab<<<BT, 256>>>(pProj, pIdx, pA2, pB2, ns_w);

    // L = [qs|kn_sum] @ [qs|k]^T + mask : per-batch 512x512, K=512
    gemm_nt<<<dim3(8, 8, Bb), 256>>>(
        pA2, pB2, pL, 512, 512, 512, Tt, sT5, sT5, sTT, 1.0f, adj, sTT, Tt, 1);

    // Gq = q @ q^T : per-batch 512x512, K=256
    gemm_nt<<<dim3(8, 8, Bb), 256>>>(
        pProj, pProj, pGq, Cc, NPROJ, NPROJ, Tt, sTP, sTP, sTT, 1.0f, nullptr, 0, 0, 0);

    add_simnn<<<dim3(Tt, Bb), 256>>>(pGq, pIdx, pL, nn_w);

    // D = mq @ mk^T * C^-0.5 : per-batch 512x512, K=256
    gemm_nt<<<dim3(8, 8, Bb), 256>>>(
        pProj + 1024, pProj + 1280, pD, Cc, NPROJ, NPROJ, Tt, sTP, sTP, sTT,
        0.0625f, nullptr, 0, 0, 0);

    softmax_rows<<<dim3(BT, 2), 256>>>(pL, pD);

    // out = softmax(L) @ v : per-batch 512x256, K=512
    gemm_nn<<<dim3(Cc / 64, Tt / 64, Bb), 256>>>(
        pL, pProj + 768, out, Tt, Tt, NPROJ, Cc, sTT, sTP, sTC, 1.0f, 0);
    // out += softmax(D) @ mv
    gemm_nn<<<dim3(Cc / 64, Tt / 64, Bb), 256>>>(
        pD, pProj + 1536, out, Tt, Tt, NPROJ, Cc, sTT, sTP, sTC, 1.0f, 2);
}

// round 4
// speedup vs baseline: 1.4886x; 1.4886x over previous
#include <cuda_runtime.h>
#include <cstdint>
#include <math.h>

#define Bb 8
#define Tt 512
#define Cc 256
#define Kk 4
constexpr int BT    = Bb * Tt;     // 4096
constexpr int NPROJ = 1792;        // [q|k|qs|v|mq|mk|mv]
constexpr float NEGV = -1e22f;

// ---- scratch -----------------------------------------------------------
__device__ float g_Wall[NPROJ * Cc];
__device__ int   g_idx [BT * Kk];
__device__ float g_proj[(long)BT * NPROJ];
__device__ float g_A2  [(long)Bb * Tt * 512];
__device__ float g_B2  [(long)Bb * Tt * 512];
__device__ float g_Gq  [(long)Bb * Tt * Tt];
__device__ float g_L   [(long)Bb * Tt * Tt];
__device__ float g_D   [(long)Bb * Tt * Tt];
__device__ float g_Vt  [2L * Bb * Cc * Tt];   // [which][b][c][t]

// ---- PTX helpers -------------------------------------------------------
__device__ __forceinline__ uint32_t smem_u32(const void* p) {
    uint32_t a;
    asm("{ .reg .u64 t; cvta.to.shared.u64 t, %1; cvt.u32.u64 %0, t; }" : "=r"(a) : "l"(p));
    return a;
}
__device__ __forceinline__ uint32_t to_tf32(float x) {
    uint32_t r;
    asm("cvt.rna.tf32.f32 %0, %1;" : "=r"(r) : "f"(x));
    return r;
}
__device__ __forceinline__ void cp16(uint32_t s, const void* g) {
    asm volatile("cp.async.cg.shared.global [%0], [%1], 16;" :: "r"(s), "l"(g));
}
__device__ __forceinline__ void cp_commit() {
    asm volatile("cp.async.commit_group;" ::: "memory");
}
__device__ __forceinline__ void cp_wait1() {
    asm volatile("cp.async.wait_group 1;" ::: "memory");
}
__device__ __forceinline__ void cp_wait0() {
    asm volatile("cp.async.wait_group 0;" ::: "memory");
}
__device__ __forceinline__ void mma_tf32(float* c, uint32_t a0, uint32_t a1, uint32_t a2,
                                         uint32_t a3, uint32_t b0, uint32_t b1) {
    asm volatile(
        "mma.sync.aligned.m16n8k8.row.col.f32.tf32.tf32.f32 "
        "{%0,%1,%2,%3}, {%4,%5,%6,%7}, {%8,%9}, {%0,%1,%2,%3};\n"
        : "+f"(c[0]), "+f"(c[1]), "+f"(c[2]), "+f"(c[3])
        : "r"(a0), "r"(a1), "r"(a2), "r"(a3), "r"(b0), "r"(b1));
}

// ---- tf32x3 tensor-core NT GEMM ---------------------------------------
// C[m,n] = alpha * sum_k A[m,k]*B[n,k]; flags: 1 = adj mask, 2 = accumulate
constexpr int STRIDE = 36;                       // padded floats per smem row
constexpr int TILE_F = 128 * STRIDE;             // floats per tile
constexpr int STAGE_F = 2 * TILE_F;              // A+B per stage
constexpr int SMEM_DYN = 2 * STAGE_F * 4;        // 73728 B

__global__ void __launch_bounds__(256)
gemm_tc(const float* __restrict__ A, const float* __restrict__ B,
        float* __restrict__ C, int Kdim, int lda, int ldb, int ldc,
        long sA, long sB, long sC, float alpha,
        const float* __restrict__ mask, long sMask, int ldm, int flags) {
    extern __shared__ float sm[];
    uint32_t sm32 = smem_u32(sm);

    int tid = threadIdx.x;
    int wid = tid >> 5, lane = tid & 31;
    int wm = wid >> 2, wn = wid & 3;             // 2 x 4 warp grid
    int lr = lane >> 2, lc = lane & 3;
    A += (long)blockIdx.z * sA;
    B += (long)blockIdx.z * sB;
    C += (long)blockIdx.z * sC;
    int m0 = blockIdx.y * 128, n0 = blockIdx.x * 128;

    // loader mapping: 256 threads, 4 rows each, 1 float4 per row per tile
    int ldrow = tid >> 3;                        // 0..31
    int ldc4  = (tid & 7) * 4;                   // col 0..28

    float c[4][4][4];
#pragma unroll
    for (int i = 0; i < 4; i++)
#pragma unroll
        for (int j = 0; j < 4; j++)
#pragma unroll
            for (int e = 0; e < 4; e++) c[i][j][e] = 0.f;

    int nch = Kdim >> 5;

    auto issue = [&](int it) {
        int buf = it & 1;
        uint32_t baseA = sm32 + buf * STAGE_F * 4;
        uint32_t baseB = baseA + TILE_F * 4;
        int k0 = it * 32;
#pragma unroll
        for (int j = 0; j < 4; j++) {
            int r = ldrow + 32 * j;
            cp16(baseA + (r * STRIDE + ldc4) * 4, A + (long)(m0 + r) * lda + k0 + ldc4);
            cp16(baseB + (r * STRIDE + ldc4) * 4, B + (long)(n0 + r) * ldb + k0 + ldc4);
        }
    };

    issue(0); cp_commit();
    for (int it = 0; it < nch; it++) {
        if (it + 1 < nch) { issue(it + 1); cp_commit(); cp_wait1(); }
        else              { cp_wait0(); }
        __syncthreads();
        const float* As = sm + (it & 1) * STAGE_F;
        const float* Bs = As + TILE_F;
#pragma unroll
        for (int ks = 0; ks < 4; ks++) {
            int kc = ks * 8 + lc;
            uint32_t ahi[4][4], alo[4][4], bhi[4][2], blo[4][2];
#pragma unroll
            for (int mt = 0; mt < 4; mt++) {
                int r0 = wm * 64 + mt * 16 + lr;
                float a0 = As[r0 * STRIDE + kc];
                float a1 = As[(r0 + 8) * STRIDE + kc];
                float a2 = As[r0 * STRIDE + kc + 4];
                float a3 = As[(r0 + 8) * STRIDE + kc + 4];
                ahi[mt][0] = to_tf32(a0); alo[mt][0] = to_tf32(a0 - __uint_as_float(ahi[mt][0]));
                ahi[mt][1] = to_tf32(a1); alo[mt][1] = to_tf32(a1 - __uint_as_float(ahi[mt][1]));
                ahi[mt][2] = to_tf32(a2); alo[mt][2] = to_tf32(a2 - __uint_as_float(ahi[mt][2]));
                ahi[mt][3] = to_tf32(a3); alo[mt][3] = to_tf32(a3 - __uint_as_float(ahi[mt][3]));
            }
#pragma unroll
            for (int nt = 0; nt < 4; nt++) {
                int rn = wn * 32 + nt * 8 + lr;
                float b0 = Bs[rn * STRIDE + kc];
                float b1 = Bs[rn * STRIDE + kc + 4];
                bhi[nt][0] = to_tf32(b0); blo[nt][0] = to_tf32(b0 - __uint_as_float(bhi[nt][0]));
                bhi[nt][1] = to_tf32(b1); blo[nt][1] = to_tf32(b1 - __uint_as_float(bhi[nt][1]));
            }
#pragma unroll
            for (int mt = 0; mt < 4; mt++)
#pragma unroll
                for (int nt = 0; nt < 4; nt++) {
                    mma_tf32(c[mt][nt], ahi[mt][0], ahi[mt][1], ahi[mt][2], ahi[mt][3],
                             bhi[nt][0], bhi[nt][1]);
                    mma_tf32(c[mt][nt], ahi[mt][0], ahi[mt][1], ahi[mt][2], ahi[mt][3],
                             blo[nt][0], blo[nt][1]);
                    mma_tf32(c[mt][nt], alo[mt][0], alo[mt][1], alo[mt][2], alo[mt][3],
                             bhi[nt][0], bhi[nt][1]);
                }
        }
        __syncthreads();
    }

    // epilogue
#pragma unroll
    for (int mt = 0; mt < 4; mt++) {
        int gm = m0 + wm * 64 + mt * 16 + lr;
#pragma unroll
        for (int nt = 0; nt < 4; nt++) {
            int gn = n0 + wn * 32 + nt * 8 + 2 * lc;
#pragma unroll
            for (int half = 0; half < 2; half++) {
                int row = gm + half * 8;
                float v0 = c[mt][nt][2 * half + 0] * alpha;
                float v1 = c[mt][nt][2 * half + 1] * alpha;
                if (flags & 1) {
                    const float2 a = *(const float2*)(mask + (long)blockIdx.z * sMask +
                                                      (long)row * ldm + gn);
                    if (a.x == 0.0f) v0 += NEGV;
                    if (a.y == 0.0f) v1 += NEGV;
                }
                float2* dst = (float2*)(C + (long)row * ldc + gn);
                if (flags & 2) {
                    float2 o = *dst;
                    o.x += v0; o.y += v1;
                    *dst = o;
                } else {
                    *dst = make_float2(v0, v1);
                }
            }
        }
    }
}

// ---- pack weights ------------------------------------------------------
__global__ void pack_w(const float* __restrict__ Wq, const float* __restrict__ Wk,
                       const float* __restrict__ Wqs, const float* __restrict__ Wv,
                       const float* __restrict__ Wqkv, float* __restrict__ Wall) {
    int i = blockIdx.x * blockDim.x + threadIdx.x;
    if (i >= NPROJ * Cc) return;
    int row = i / Cc, col = i % Cc;
    float v;
    if      (row <  256) v = Wq  [ row         * Cc + col];
    else if (row <  512) v = Wk  [(row -  256) * Cc + col];
    else if (row <  768) v = Wqs [(row -  512) * Cc + col];
    else if (row < 1024) v = Wv  [(row -  768) * Cc + col];
    else                 v = Wqkv[(row - 1024) * Cc + col];
    Wall[i] = v;
}

// ---- idx from one-hot (warp per row) -----------------------------------
__global__ void extract_idx(const float* __restrict__ inxs, int* __restrict__ idx) {
    int w = (blockIdx.x * blockDim.x + threadIdx.x) >> 5;
    int lane = threadIdx.x & 31;
    if (w >= BT * Kk) return;
    const float4* p = (const float4*)(inxs + (long)w * Tt);
    int found = 0;
    for (int j = lane; j < Tt / 4; j += 32) {
        float4 v = p[j];
        if (v.x > 0.5f) found = 4 * j;
        if (v.y > 0.5f) found = 4 * j + 1;
        if (v.z > 0.5f) found = 4 * j + 2;
        if (v.w > 0.5f) found = 4 * j + 3;
    }
#pragma unroll
    for (int d = 16; d > 0; d >>= 1)
        found = max(found, __shfl_xor_sync(0xffffffffu, found, d));
    if (lane == 0) idx[w] = found;
}

// ---- l2-normalize q,k,qs segments --------------------------------------
__global__ void normalize_rows(float* __restrict__ proj) {
    long row = blockIdx.x;
    int tid = threadIdx.x;
    __shared__ float red[8];
    __shared__ float bcast;
    for (int seg = 0; seg < 3; seg++) {
        long o = row * NPROJ + seg * 256 + tid;
        float v = proj[o];
        float ss = v * v;
#pragma unroll
        for (int d = 16; d > 0; d >>= 1) ss += __shfl_xor_sync(0xffffffffu, ss, d);
        if ((tid & 31) == 0) red[tid >> 5] = ss;
        __syncthreads();
        if (tid == 0) {
            float s = 0.f;
            for (int i = 0; i < 8; i++) s += red[i];
            bcast = 1.0f / fmaxf(sqrtf(s), 1e-12f);
        }
        __syncthreads();
        proj[o] = v * bcast;
        __syncthreads();
    }
}

// ---- build [qs|kn_sum] and [qs|k] --------------------------------------
__global__ void build_ab(const float* __restrict__ proj, const int* __restrict__ idx,
                         float* __restrict__ A2, float* __restrict__ B2,
                         const float* __restrict__ ns_w) {
    int row = blockIdx.x;
    int c = threadIdx.x;
    int b = row >> 9;
    long pbase = (long)row * NPROJ;
    float qs = proj[pbase + 512 + c];
    float kv = proj[pbase + 256 + c];
    long o = (long)row * 512;
    B2[o + c] = qs;
    B2[o + 256 + c] = kv;
    A2[o + c] = qs;
    float s = 0.f;
#pragma unroll
    for (int n = 0; n < Kk; n++) {
        int t = idx[row * Kk + n];
        s += ns_w[n] * proj[((long)(b * Tt + t)) * NPROJ + 256 + c];
    }
    A2[o + 256 + c] = s;
}

// ---- transpose v/mv into K-major [2][B][C][T] --------------------------
__global__ void transpose_v(const float* __restrict__ proj, float* __restrict__ Vt) {
    __shared__ float tile[32][33];
    int which = blockIdx.z >> 3;
    int b = blockIdx.z & 7;
    int t0 = blockIdx.x * 32, c0 = blockIdx.y * 32;
    int tx = threadIdx.x & 31, ty = threadIdx.x >> 5;
    int srcCol = (which ? 1536 : 768) + c0;
    for (int i = ty; i < 32; i += 8)
        tile[i][tx] = proj[((long)(b * Tt + t0 + i)) * NPROJ + srcCol + tx];
    __syncthreads();
    float* dst = Vt + (((long)which * Bb + b) * Cc + c0) * (long)Tt + t0;
    for (int i = ty; i < 32; i += 8)
        dst[(long)i * Tt + tx] = tile[tx][i];
}

// ---- sim_nn gather/max --------------------------------------------------
__global__ void add_simnn(const float* __restrict__ Gq, const int* __restrict__ idx,
                          float* __restrict__ L, const float* __restrict__ nn_w) {
    int i = blockIdx.x, b = blockIdx.y;
    int tid = threadIdx.x;
    __shared__ float srow[4][Tt];
    __shared__ int   sjdx[Tt * Kk];
    __shared__ float w[4];
    if (tid < 4) w[tid] = nn_w[tid];
    for (int j = tid; j < Tt * Kk; j += 256) sjdx[j] = idx[b * Tt * Kk + j];
#pragma unroll
    for (int x = 0; x < 4; x++) {
        int rx = idx[(b * Tt + i) * Kk + x];
        for (int c = tid; c < Tt; c += 256)
            srow[x][c] = Gq[((long)b * Tt + rx) * Tt + c];
    }
    __syncthreads();
    for (int j = tid; j < Tt; j += 256) {
        float acc = 0.f;
#pragma unroll
        for (int x = 0; x < 4; x++) {
            float m = -3.4e38f;
#pragma unroll
            for (int y = 0; y < 4; y++)
                m = fmaxf(m, srow[x][sjdx[j * Kk + y]]);
            acc += w[x] * m;
        }
        L[((long)b * Tt + i) * Tt + j] += acc;
    }
}

// ---- row softmax -------------------------------------------------------
__global__ void softmax_rows(float* __restrict__ L, float* __restrict__ D) {
    float* p = (blockIdx.y == 0 ? L : D) + (long)blockIdx.x * Tt;
    int tid = threadIdx.x;
    __shared__ float red[8];
    __shared__ float bcast;
    float2 v = ((float2*)p)[tid];
    float m = fmaxf(v.x, v.y);
#pragma unroll
    for (int d = 16; d > 0; d >>= 1) m = fmaxf(m, __shfl_xor_sync(0xffffffffu, m, d));
    if ((tid & 31) == 0) red[tid >> 5] = m;
    __syncthreads();
    if (tid == 0) {
        float mm = red[0];
        for (int i = 1; i < 8; i++) mm = fmaxf(mm, red[i]);
        bcast = mm;
    }
    __syncthreads();
    float mm = bcast;
    float e0 = __expf(v.x - mm), e1 = __expf(v.y - mm);
    float s = e0 + e1;
#pragma unroll
    for (int d = 16; d > 0; d >>= 1) s += __shfl_xor_sync(0xffffffffu, s, d);
    if ((tid & 31) == 0) red[tid >> 5] = s;
    __syncthreads();
    if (tid == 0) {
        float ss = 0.f;
        for (int i = 0; i < 8; i++) ss += red[i];
        bcast = 1.0f / ss;
    }
    __syncthreads();
    float inv = bcast;
    ((float2*)p)[tid] = make_float2(e0 * inv, e1 * inv);
}

// ---- host --------------------------------------------------------------
extern "C" void kernel_launch(void* const* d_in, const int* in_sizes, int n_in,
                              void* d_out, int out_size) {
    const float* x    = (const float*)d_in[0];
    const float* adj  = (const float*)d_in[1];
    const float* inxs = (const float*)d_in[2];
    const float* Wq   = (const float*)d_in[3];
    const float* Wk   = (const float*)d_in[4];
    const float* Wqs  = (const float*)d_in[5];
    const float* Wv   = (const float*)d_in[6];
    const float* nn_w = (const float*)d_in[7];
    const float* ns_w = (const float*)d_in[8];
    const float* Wqkv = (const float*)d_in[9];
    float* out = (float*)d_out;

    float *pWall, *pProj, *pA2, *pB2, *pGq, *pL, *pD, *pVt; int* pIdx;
    cudaGetSymbolAddress((void**)&pWall, g_Wall);
    cudaGetSymbolAddress((void**)&pIdx,  g_idx);
    cudaGetSymbolAddress((void**)&pProj, g_proj);
    cudaGetSymbolAddress((void**)&pA2,   g_A2);
    cudaGetSymbolAddress((void**)&pB2,   g_B2);
    cudaGetSymbolAddress((void**)&pGq,   g_Gq);
    cudaGetSymbolAddress((void**)&pL,    g_L);
    cudaGetSymbolAddress((void**)&pD,    g_D);
    cudaGetSymbolAddress((void**)&pVt,   g_Vt);

    cudaFuncSetAttribute(gemm_tc, cudaFuncAttributeMaxDynamicSharedMemorySize, SMEM_DYN);

    const long sTT = (long)Tt * Tt;
    const long sTP = (long)Tt * NPROJ;
    const long sT5 = (long)Tt * 512;
    const long sTC = (long)Tt * Cc;
    const long sVT = (long)Cc * Tt;

    pack_w<<<(NPROJ * Cc + 255) / 256, 256>>>(Wq, Wk, Wqs, Wv, Wqkv, pWall);
    extract_idx<<<(BT * Kk * 32 + 255) / 256, 256>>>(inxs, pIdx);

    // proj = x @ Wall^T : (4096 x 1792), K=256
    gemm_tc<<<dim3(NPROJ / 128, BT / 128, 1), 256, SMEM_DYN>>>(
        x, pWall, pProj, Cc, Cc, Cc, NPROJ, 0, 0, 0, 1.0f, nullptr, 0, 0, 0);

    transpose_v<<<dim3(Tt / 32, Cc / 32, 2 * Bb), 256>>>(pProj, pVt);
    normalize_rows<<<BT, 256>>>(pProj);
    build_ab<<<BT, 256>>>(pProj, pIdx, pA2, pB2, ns_w);

    // L = [qs|kn_sum] @ [qs|k]^T + mask : per-batch 512x512, K=512
    gemm_tc<<<dim3(4, 4, Bb), 256, SMEM_DYN>>>(
        pA2, pB2, pL, 512, 512, 512, Tt, sT5, sT5, sTT, 1.0f, adj, sTT, Tt, 1);

    // Gq = q @ q^T : per-batch 512x512, K=256
    gemm_tc<<<dim3(4, 4, Bb), 256, SMEM_DYN>>>(
        pProj, pProj, pGq, Cc, NPROJ, NPROJ, Tt, sTP, sTP, sTT, 1.0f, nullptr, 0, 0, 0);

    add_simnn<<<dim3(Tt, Bb), 256>>>(pGq, pIdx, pL, nn_w);

    // D = mq @ mk^T * C^-0.5
    gemm_tc<<<dim3(4, 4, Bb), 256, SMEM_DYN>>>(
        pProj + 1024, pProj + 1280, pD, Cc, NPROJ, NPROJ, Tt, sTP, sTP, sTT,
        0.0625f, nullptr, 0, 0, 0);

    softmax_rows<<<dim3(BT, 2), 256>>>(pL, pD);

    // out = softmax(L) @ v  (Vt is K-major: [c][t])
    gemm_tc<<<dim3(Cc / 128, Tt / 128, Bb), 256, SMEM_DYN>>>(
        pL, pVt, out, Tt, Tt, Tt, Cc, sTT, sVT, sTC, 1.0f, nullptr, 0, 0, 0);
    // out += softmax(D) @ mv
    gemm_tc<<<dim3(Cc / 128, Tt / 128, Bb), 256, SMEM_DYN>>>(
        pD, pVt + (long)Bb * Cc * Tt, out, Tt, Tt, Tt, Cc, sTT, sVT, sTC, 1.0f,
        nullptr, 0, 0, 2);
}

// round 5
// speedup vs baseline: 1.8069x; 1.2138x over previous
#include <cuda_runtime.h>
#include <cuda_fp16.h>
#include <cstdint>
#include <math.h>

#define Bb 8
#define Tt 512
#define Cc 256
#define Kk 4
constexpr int BT    = Bb * Tt;     // 4096
constexpr int NPROJ = 1792;        // [q|k|qs|v|mq|mk|mv]
constexpr float NEGV = -1e22f;

// ---- scratch -----------------------------------------------------------
__device__ float g_Wall[NPROJ * Cc];
__device__ int   g_idx [BT * Kk];
__device__ float g_proj[(long)BT * NPROJ];
__device__ float g_A2  [(long)Bb * Tt * 512];
__device__ float g_B2  [(long)Bb * Tt * 512];
__device__ float g_Gq  [(long)Bb * Tt * Tt];
__device__ float g_LD  [(long)Bb * Tt * 1024];  // [b][t][ L(512) | D(512) ]
__device__ float g_Vt  [(long)Bb * Cc * 1024];  // [b][c][ v_t(512) | mv_t(512) ]

// ---- PTX helpers -------------------------------------------------------
__device__ __forceinline__ uint32_t smem_u32(const void* p) {
    uint32_t a;
    asm("{ .reg .u64 t; cvta.to.shared.u64 t, %1; cvt.u32.u64 %0, t; }" : "=r"(a) : "l"(p));
    return a;
}
__device__ __forceinline__ void cp16(uint32_t s, const void* g) {
    asm volatile("cp.async.cg.shared.global [%0], [%1], 16;" :: "r"(s), "l"(g));
}
__device__ __forceinline__ void cp_commit() {
    asm volatile("cp.async.commit_group;" ::: "memory");
}
__device__ __forceinline__ void cp_wait1() {
    asm volatile("cp.async.wait_group 1;" ::: "memory");
}
__device__ __forceinline__ void cp_wait0() {
    asm volatile("cp.async.wait_group 0;" ::: "memory");
}
__device__ __forceinline__ void mma_f16(float* c, uint32_t a0, uint32_t a1, uint32_t a2,
                                        uint32_t a3, uint32_t b0, uint32_t b1) {
    asm volatile(
        "mma.sync.aligned.m16n8k16.row.col.f32.f16.f16.f32 "
        "{%0,%1,%2,%3}, {%4,%5,%6,%7}, {%8,%9}, {%0,%1,%2,%3};\n"
        : "+f"(c[0]), "+f"(c[1]), "+f"(c[2]), "+f"(c[3])
        : "r"(a0), "r"(a1), "r"(a2), "r"(a3), "r"(b0), "r"(b1));
}
// split float2 (k-adjacent pair) into fp16x2 hi and fp16x2 lo packed regs
__device__ __forceinline__ void split_h2(float2 v, uint32_t& hi, uint32_t& lo) {
    __half2 h = __float22half2_rn(v);
    float2 hf = __half22float2(h);
    __half2 l = __float22half2_rn(make_float2(v.x - hf.x, v.y - hf.y));
    hi = *(uint32_t*)&h;
    lo = *(uint32_t*)&l;
}

// ---- fp16x3 tensor-core NT GEMM ---------------------------------------
// C[m,n] = alpha * sum_k A[m,k]*B[n,k]; flags: 1 = adj mask, 2 = accumulate
constexpr int STRIDE = 36;                       // padded floats per smem row
constexpr int TILE_F = 128 * STRIDE;
constexpr int STAGE_F = 2 * TILE_F;              // A+B per stage
constexpr int SMEM_DYN = 2 * STAGE_F * 4;        // 73728 B

__global__ void __launch_bounds__(512)
gemm_tc(const float* __restrict__ A, const float* __restrict__ B,
        float* __restrict__ C, int Kdim, int lda, int ldb, int ldc,
        long sA, long sB, long sC, float alpha,
        const float* __restrict__ mask, long sMask, int ldm, int flags) {
    extern __shared__ float sm[];
    uint32_t sm32 = smem_u32(sm);

    int tid = threadIdx.x;
    int wid = tid >> 5, lane = tid & 31;
    int wm = wid >> 2, wn = wid & 3;             // 4 x 4 warp grid, 32x32 tiles
    int lr = lane >> 2, lc = lane & 3;
    A += (long)blockIdx.z * sA;
    B += (long)blockIdx.z * sB;
    C += (long)blockIdx.z * sC;
    int m0 = blockIdx.y * 128, n0 = blockIdx.x * 128;

    // loader: 512 threads, 2 rows each per tile, 1 float4 per row
    int ldrow = tid >> 3;                        // 0..63
    int ldc4  = (tid & 7) * 4;                   // 0..28

    float c[2][4][4];
#pragma unroll
    for (int i = 0; i < 2; i++)
#pragma unroll
        for (int j = 0; j < 4; j++)
#pragma unroll
            for (int e = 0; e < 4; e++) c[i][j][e] = 0.f;

    int nch = Kdim >> 5;

    auto issue = [&](int it) {
        int buf = it & 1;
        uint32_t baseA = sm32 + buf * STAGE_F * 4;
        uint32_t baseB = baseA + TILE_F * 4;
        int k0 = it * 32;
#pragma unroll
        for (int j = 0; j < 2; j++) {
            int r = ldrow + 64 * j;
            cp16(baseA + (r * STRIDE + ldc4) * 4, A + (long)(m0 + r) * lda + k0 + ldc4);
            cp16(baseB + (r * STRIDE + ldc4) * 4, B + (long)(n0 + r) * ldb + k0 + ldc4);
        }
    };

    issue(0); cp_commit();
    for (int it = 0; it < nch; it++) {
        if (it + 1 < nch) { issue(it + 1); cp_commit(); cp_wait1(); }
        else              { cp_wait0(); }
        __syncthreads();
        const float* As = sm + (it & 1) * STAGE_F;
        const float* Bs = As + TILE_F;
#pragma unroll
        for (int ks = 0; ks < 2; ks++) {
            int kb = ks * 16 + 2 * lc;
            uint32_t ahi[2][4], alo[2][4], bhi[4][2], blo[4][2];
#pragma unroll
            for (int mt = 0; mt < 2; mt++) {
                int r0 = wm * 32 + mt * 16 + lr;
                float2 e0 = *(const float2*)(As + r0 * STRIDE + kb);
                float2 e1 = *(const float2*)(As + (r0 + 8) * STRIDE + kb);
                float2 e2 = *(const float2*)(As + r0 * STRIDE + kb + 8);
                float2 e3 = *(const float2*)(As + (r0 + 8) * STRIDE + kb + 8);
                split_h2(e0, ahi[mt][0], alo[mt][0]);
                split_h2(e1, ahi[mt][1], alo[mt][1]);
                split_h2(e2, ahi[mt][2], alo[mt][2]);
                split_h2(e3, ahi[mt][3], alo[mt][3]);
            }
#pragma unroll
            for (int nt = 0; nt < 4; nt++) {
                int rn = wn * 32 + nt * 8 + lr;
                float2 f0 = *(const float2*)(Bs + rn * STRIDE + kb);
                float2 f1 = *(const float2*)(Bs + rn * STRIDE + kb + 8);
                split_h2(f0, bhi[nt][0], blo[nt][0]);
                split_h2(f1, bhi[nt][1], blo[nt][1]);
            }
#pragma unroll
            for (int mt = 0; mt < 2; mt++)
#pragma unroll
                for (int nt = 0; nt < 4; nt++) {
                    mma_f16(c[mt][nt], ahi[mt][0], ahi[mt][1], ahi[mt][2], ahi[mt][3],
                            bhi[nt][0], bhi[nt][1]);
                    mma_f16(c[mt][nt], ahi[mt][0], ahi[mt][1], ahi[mt][2], ahi[mt][3],
                            blo[nt][0], blo[nt][1]);
                    mma_f16(c[mt][nt], alo[mt][0], alo[mt][1], alo[mt][2], alo[mt][3],
                            bhi[nt][0], bhi[nt][1]);
                }
        }
        __syncthreads();
    }

    // epilogue
#pragma unroll
    for (int mt = 0; mt < 2; mt++) {
        int gm = m0 + wm * 32 + mt * 16 + lr;
#pragma unroll
        for (int nt = 0; nt < 4; nt++) {
            int gn = n0 + wn * 32 + nt * 8 + 2 * lc;
#pragma unroll
            for (int half = 0; half < 2; half++) {
                int row = gm + half * 8;
                float v0 = c[mt][nt][2 * half + 0] * alpha;
                float v1 = c[mt][nt][2 * half + 1] * alpha;
                if (flags & 1) {
                    const float2 a = *(const float2*)(mask + (long)blockIdx.z * sMask +
                                                      (long)row * ldm + gn);
                    if (a.x == 0.0f) v0 += NEGV;
                    if (a.y == 0.0f) v1 += NEGV;
                }
                float2* dst = (float2*)(C + (long)row * ldc + gn);
                if (flags & 2) {
                    float2 o = *dst;
                    o.x += v0; o.y += v1;
                    *dst = o;
                } else {
                    *dst = make_float2(v0, v1);
                }
            }
        }
    }
}

// ---- pack weights ------------------------------------------------------
__global__ void pack_w(const float* __restrict__ Wq, const float* __restrict__ Wk,
                       const float* __restrict__ Wqs, const float* __restrict__ Wv,
                       const float* __restrict__ Wqkv, float* __restrict__ Wall) {
    int i = blockIdx.x * blockDim.x + threadIdx.x;
    if (i >= NPROJ * Cc) return;
    int row = i / Cc, col = i % Cc;
    float v;
    if      (row <  256) v = Wq  [ row         * Cc + col];
    else if (row <  512) v = Wk  [(row -  256) * Cc + col];
    else if (row <  768) v = Wqs [(row -  512) * Cc + col];
    else if (row < 1024) v = Wv  [(row -  768) * Cc + col];
    else                 v = Wqkv[(row - 1024) * Cc + col];
    Wall[i] = v;
}

// ---- idx from one-hot (warp per row) -----------------------------------
__global__ void extract_idx(const float* __restrict__ inxs, int* __restrict__ idx) {
    int w = (blockIdx.x * blockDim.x + threadIdx.x) >> 5;
    int lane = threadIdx.x & 31;
    if (w >= BT * Kk) return;
    const float4* p = (const float4*)(inxs + (long)w * Tt);
    int found = 0;
    for (int j = lane; j < Tt / 4; j += 32) {
        float4 v = p[j];
        if (v.x > 0.5f) found = 4 * j;
        if (v.y > 0.5f) found = 4 * j + 1;
        if (v.z > 0.5f) found = 4 * j + 2;
        if (v.w > 0.5f) found = 4 * j + 3;
    }
#pragma unroll
    for (int d = 16; d > 0; d >>= 1)
        found = max(found, __shfl_xor_sync(0xffffffffu, found, d));
    if (lane == 0) idx[w] = found;
}

// ---- l2-normalize q,k,qs segments --------------------------------------
__global__ void normalize_rows(float* __restrict__ proj) {
    long row = blockIdx.x;
    int tid = threadIdx.x;
    __shared__ float red[8];
    __shared__ float bcast;
    for (int seg = 0; seg < 3; seg++) {
        long o = row * NPROJ + seg * 256 + tid;
        float v = proj[o];
        float ss = v * v;
#pragma unroll
        for (int d = 16; d > 0; d >>= 1) ss += __shfl_xor_sync(0xffffffffu, ss, d);
        if ((tid & 31) == 0) red[tid >> 5] = ss;
        __syncthreads();
        if (tid == 0) {
            float s = 0.f;
            for (int i = 0; i < 8; i++) s += red[i];
            bcast = 1.0f / fmaxf(sqrtf(s), 1e-12f);
        }
        __syncthreads();
        proj[o] = v * bcast;
        __syncthreads();
    }
}

// ---- build [qs|kn_sum] and [qs|k] --------------------------------------
__global__ void build_ab(const float* __restrict__ proj, const int* __restrict__ idx,
                         float* __restrict__ A2, float* __restrict__ B2,
                         const float* __restrict__ ns_w) {
    int row = blockIdx.x;
    int c = threadIdx.x;
    int b = row >> 9;
    long pbase = (long)row * NPROJ;
    float qs = proj[pbase + 512 + c];
    float kv = proj[pbase + 256 + c];
    long o = (long)row * 512;
    B2[o + c] = qs;
    B2[o + 256 + c] = kv;
    A2[o + c] = qs;
    float s = 0.f;
#pragma unroll
    for (int n = 0; n < Kk; n++) {
        int t = idx[row * Kk + n];
        s += ns_w[n] * proj[((long)(b * Tt + t)) * NPROJ + 256 + c];
    }
    A2[o + 256 + c] = s;
}

// ---- transpose v/mv into [b][c][ v_t | mv_t ] --------------------------
__global__ void transpose_v(const float* __restrict__ proj, float* __restrict__ Vt) {
    __shared__ float tile[32][33];
    int which = blockIdx.z >> 3;
    int b = blockIdx.z & 7;
    int t0 = blockIdx.x * 32, c0 = blockIdx.y * 32;
    int tx = threadIdx.x & 31, ty = threadIdx.x >> 5;
    int srcCol = (which ? 1536 : 768) + c0;
    for (int i = ty; i < 32; i += 8)
        tile[i][tx] = proj[((long)(b * Tt + t0 + i)) * NPROJ + srcCol + tx];
    __syncthreads();
    float* dst = Vt + ((long)b * Cc + c0) * 1024 + which * 512 + t0;
    for (int i = ty; i < 32; i += 8)
        dst[(long)i * 1024 + tx] = tile[tx][i];
}

// ---- sim_nn gather/max (adds into L half of LD) ------------------------
__global__ void add_simnn(const float* __restrict__ Gq, const int* __restrict__ idx,
                          float* __restrict__ LD, const float* __restrict__ nn_w) {
    int i = blockIdx.x, b = blockIdx.y;
    int tid = threadIdx.x;
    __shared__ float srow[4][Tt];
    __shared__ int   sjdx[Tt * Kk];
    __shared__ float w[4];
    if (tid < 4) w[tid] = nn_w[tid];
    for (int j = tid; j < Tt * Kk; j += 256) sjdx[j] = idx[b * Tt * Kk + j];
#pragma unroll
    for (int x = 0; x < 4; x++) {
        int rx = idx[(b * Tt + i) * Kk + x];
        for (int c = tid; c < Tt; c += 256)
            srow[x][c] = Gq[((long)b * Tt + rx) * Tt + c];
    }
    __syncthreads();
    for (int j = tid; j < Tt; j += 256) {
        float acc = 0.f;
#pragma unroll
        for (int x = 0; x < 4; x++) {
            float m = -3.4e38f;
#pragma unroll
            for (int y = 0; y < 4; y++)
                m = fmaxf(m, srow[x][sjdx[j * Kk + y]]);
            acc += w[x] * m;
        }
        LD[((long)b * Tt + i) * 1024 + j] += acc;
    }
}

// ---- row softmax over halves of LD -------------------------------------
__global__ void softmax_rows(float* __restrict__ LD) {
    float* p = LD + (long)blockIdx.x * 1024 + blockIdx.y * 512;
    int tid = threadIdx.x;
    __shared__ float red[8];
    __shared__ float bcast;
    float2 v = ((float2*)p)[tid];
    float m = fmaxf(v.x, v.y);
#pragma unroll
    for (int d = 16; d > 0; d >>= 1) m = fmaxf(m, __shfl_xor_sync(0xffffffffu, m, d));
    if ((tid & 31) == 0) red[tid >> 5] = m;
    __syncthreads();
    if (tid == 0) {
        float mm = red[0];
        for (int i = 1; i < 8; i++) mm = fmaxf(mm, red[i]);
        bcast = mm;
    }
    __syncthreads();
    float mm = bcast;
    float e0 = __expf(v.x - mm), e1 = __expf(v.y - mm);
    float s = e0 + e1;
#pragma unroll
    for (int d = 16; d > 0; d >>= 1) s += __shfl_xor_sync(0xffffffffu, s, d);
    if ((tid & 31) == 0) red[tid >> 5] = s;
    __syncthreads();
    if (tid == 0) {
        float ss = 0.f;
        for (int i = 0; i < 8; i++) ss += red[i];
        bcast = 1.0f / ss;
    }
    __syncthreads();
    float inv = bcast;
    ((float2*)p)[tid] = make_float2(e0 * inv, e1 * inv);
}

// ---- host --------------------------------------------------------------
extern "C" void kernel_launch(void* const* d_in, const int* in_sizes, int n_in,
                              void* d_out, int out_size) {
    const float* x    = (const float*)d_in[0];
    const float* adj  = (const float*)d_in[1];
    const float* inxs = (const float*)d_in[2];
    const float* Wq   = (const float*)d_in[3];
    const float* Wk   = (const float*)d_in[4];
    const float* Wqs  = (const float*)d_in[5];
    const float* Wv   = (const float*)d_in[6];
    const float* nn_w = (const float*)d_in[7];
    const float* ns_w = (const float*)d_in[8];
    const float* Wqkv = (const float*)d_in[9];
    float* out = (float*)d_out;

    float *pWall, *pProj, *pA2, *pB2, *pGq, *pLD, *pVt; int* pIdx;
    cudaGetSymbolAddress((void**)&pWall, g_Wall);
    cudaGetSymbolAddress((void**)&pIdx,  g_idx);
    cudaGetSymbolAddress((void**)&pProj, g_proj);
    cudaGetSymbolAddress((void**)&pA2,   g_A2);
    cudaGetSymbolAddress((void**)&pB2,   g_B2);
    cudaGetSymbolAddress((void**)&pGq,   g_Gq);
    cudaGetSymbolAddress((void**)&pLD,   g_LD);
    cudaGetSymbolAddress((void**)&pVt,   g_Vt);

    cudaFuncSetAttribute(gemm_tc, cudaFuncAttributeMaxDynamicSharedMemorySize, SMEM_DYN);

    const long sTT  = (long)Tt * Tt;
    const long sTP  = (long)Tt * NPROJ;
    const long sT5  = (long)Tt * 512;
    const long sTLD = (long)Tt * 1024;
    const long sTC  = (long)Tt * Cc;
    const long sVT  = (long)Cc * 1024;

    pack_w<<<(NPROJ * Cc + 255) / 256, 256>>>(Wq, Wk, Wqs, Wv, Wqkv, pWall);
    extract_idx<<<(BT * Kk * 32 + 255) / 256, 256>>>(inxs, pIdx);

    // proj = x @ Wall^T : (4096 x 1792), K=256
    gemm_tc<<<dim3(NPROJ / 128, BT / 128, 1), 512, SMEM_DYN>>>(
        x, pWall, pProj, Cc, Cc, Cc, NPROJ, 0, 0, 0, 1.0f, nullptr, 0, 0, 0);

    transpose_v<<<dim3(Tt / 32, Cc / 32, 2 * Bb), 256>>>(pProj, pVt);
    normalize_rows<<<BT, 256>>>(pProj);
    build_ab<<<BT, 256>>>(pProj, pIdx, pA2, pB2, ns_w);

    // L half of LD = [qs|kn_sum] @ [qs|k]^T + mask : per-batch 512x512, K=512
    gemm_tc<<<dim3(4, 4, Bb), 512, SMEM_DYN>>>(
        pA2, pB2, pLD, 512, 512, 512, 1024, sT5, sT5, sTLD, 1.0f, adj, sTT, Tt, 1);

    // Gq = q @ q^T : per-batch 512x512, K=256
    gemm_tc<<<dim3(4, 4, Bb), 512, SMEM_DYN>>>(
        pProj, pProj, pGq, Cc, NPROJ, NPROJ, Tt, sTP, sTP, sTT, 1.0f, nullptr, 0, 0, 0);

    add_simnn<<<dim3(Tt, Bb), 256>>>(pGq, pIdx, pLD, nn_w);

    // D half of LD = mq @ mk^T * C^-0.5
    gemm_tc<<<dim3(4, 4, Bb), 512, SMEM_DYN>>>(
        pProj + 1024, pProj + 1280, pLD + 512, Cc, NPROJ, NPROJ, 1024, sTP, sTP, sTLD,
        0.0625f, nullptr, 0, 0, 0);

    softmax_rows<<<dim3(BT, 2), 256>>>(pLD);

    // out = [P_L | P_D] @ [v | mv]^T(K-major) : per-batch 512x256, K=1024
    gemm_tc<<<dim3(Cc / 128, Tt / 128, Bb), 512, SMEM_DYN>>>(
        pLD, pVt, out, 1024, 1024, 1024, Cc, sTLD, sVT, sTC, 1.0f, nullptr, 0, 0, 0);
}

// round 7
// speedup vs baseline: 2.1304x; 1.1790x over previous
#include <cuda_runtime.h>
#include <cuda_fp16.h>
#include <cstdint>
#include <math.h>

#define Bb 8
#define Tt 512
#define Cc 256
#define Kk 4
constexpr int BT    = Bb * Tt;     // 4096
constexpr int NPROJ = 1792;        // [q|k|qs|v|mq|mk|mv]
constexpr float NEGV = -1e22f;

// ---- scratch -----------------------------------------------------------
__device__ __half gh_Wall[NPROJ * Cc];
__device__ __half gl_Wall[NPROJ * Cc];
__device__ __half gh_x[BT * Cc];
__device__ __half gl_x[BT * Cc];
__device__ int    g_idx [BT * Kk];
__device__ float  g_proj[(long)BT * NPROJ];
__device__ __half gh_qmm[(long)BT * 768];   // [q|mq|mk] hi
__device__ __half gl_qmm[(long)BT * 768];
__device__ __half gh_A2[(long)BT * 512];
__device__ __half gl_A2[(long)BT * 512];
__device__ __half gh_B2[(long)BT * 512];
__device__ __half gl_B2[(long)BT * 512];
__device__ float  g_Gq [(long)Bb * Tt * Tt];
__device__ float  g_LD [(long)BT * 1024];   // logits [L|D]
__device__ __half gh_P [(long)BT * 1024];   // probs hi
__device__ __half gl_P [(long)BT * 1024];
__device__ __half gh_Vt[(long)Bb * Cc * 1024];
__device__ __half gl_Vt[(long)Bb * Cc * 1024];

// ---- PTX helpers -------------------------------------------------------
__device__ __forceinline__ uint32_t smem_u32(const void* p) {
    uint32_t a;
    asm("{ .reg .u64 t; cvta.to.shared.u64 t, %1; cvt.u32.u64 %0, t; }" : "=r"(a) : "l"(p));
    return a;
}
__device__ __forceinline__ void cp16(uint32_t s, const void* g) {
    asm volatile("cp.async.cg.shared.global [%0], [%1], 16;" :: "r"(s), "l"(g));
}
__device__ __forceinline__ void cp_commit() {
    asm volatile("cp.async.commit_group;" ::: "memory");
}
__device__ __forceinline__ void cp_wait1() {
    asm volatile("cp.async.wait_group 1;" ::: "memory");
}
__device__ __forceinline__ void cp_wait0() {
    asm volatile("cp.async.wait_group 0;" ::: "memory");
}
__device__ __forceinline__ void ldsm4(uint32_t& r0, uint32_t& r1, uint32_t& r2,
                                      uint32_t& r3, uint32_t a) {
    asm volatile("ldmatrix.sync.aligned.m8n8.x4.shared.b16 {%0,%1,%2,%3}, [%4];"
                 : "=r"(r0), "=r"(r1), "=r"(r2), "=r"(r3) : "r"(a));
}
__device__ __forceinline__ void mma_f16(float* c, uint32_t a0, uint32_t a1, uint32_t a2,
                                        uint32_t a3, uint32_t b0, uint32_t b1) {
    asm volatile(
        "mma.sync.aligned.m16n8k16.row.col.f32.f16.f16.f32 "
        "{%0,%1,%2,%3}, {%4,%5,%6,%7}, {%8,%9}, {%0,%1,%2,%3};\n"
        : "+f"(c[0]), "+f"(c[1]), "+f"(c[2]), "+f"(c[3])
        : "r"(a0), "r"(a1), "r"(a2), "r"(a3), "r"(b0), "r"(b1));
}
__device__ __forceinline__ void split1(float v, __half* h, __half* l) {
    __half hh = __float2half_rn(v);
    *h = hh;
    *l = __float2half_rn(v - __half2float(hh));
}

// ---- fp16x3 tensor-core NT GEMM (pre-split hi/lo inputs) ---------------
// C[m,n] = alpha * sum_k A[m,k]*B[n,k]; flags: 1 = adj mask, 2 = accumulate
constexpr int HSTR   = 40;                   // padded halves per smem row
constexpr int TILE_B = 128 * HSTR * 2;       // bytes per tile (10240)
constexpr int STAGE_B = 4 * TILE_B;          // Ah,Al,Bh,Bl (40960)
constexpr int SMEM_DYN = 2 * STAGE_B;        // 81920 B

__global__ void __launch_bounds__(512)
gemm_h(const __half* __restrict__ Ah, const __half* __restrict__ Al,
       const __half* __restrict__ Bh, const __half* __restrict__ Bl,
       float* __restrict__ C, int Kdim, int lda, int ldb, int ldc,
       long sA, long sB, long sC, float alpha,
       const float* __restrict__ mask, long sMask, int ldm, int flags) {
    extern __shared__ char sm[];
    uint32_t sm32 = smem_u32(sm);

    int tid = threadIdx.x;
    int wid = tid >> 5, lane = tid & 31;
    int wm = wid >> 2, wn = wid & 3;             // 4x4 warp grid, 32x32 tiles
    int lr = lane >> 2, lc = lane & 3;
    Ah += (long)blockIdx.z * sA;  Al += (long)blockIdx.z * sA;
    Bh += (long)blockIdx.z * sB;  Bl += (long)blockIdx.z * sB;
    C  += (long)blockIdx.z * sC;
    int m0 = blockIdx.y * 128, n0 = blockIdx.x * 128;

    // loader: 512 threads, 1 cp16 per tile each
    int ldrow = tid >> 2;                        // 0..127
    int ldc8  = (tid & 3) * 8;                   // halves 0,8,16,24

    // ldmatrix lane bases (halves offsets within tile)
    int aRow = wm * 32 + (lane & 15);
    int aK8  = (lane >> 4) * 8;
    int quad = lane >> 3, rb = lane & 7;
    int bRow = wn * 32 + (quad >> 1) * 8 + rb;
    int bK8  = (quad & 1) * 8;

    float c[2][4][4];
#pragma unroll
    for (int i = 0; i < 2; i++)
#pragma unroll
        for (int j = 0; j < 4; j++)
#pragma unroll
            for (int e = 0; e < 4; e++) c[i][j][e] = 0.f;

    int nch = Kdim >> 5;

    auto issue = [&](int it) {
        uint32_t base = sm32 + (it & 1) * STAGE_B;
        int k0 = it * 32;
        uint32_t dst = base + (ldrow * HSTR + ldc8) * 2;
        cp16(dst,              Ah + (long)(m0 + ldrow) * lda + k0 + ldc8);
        cp16(dst + TILE_B,     Al + (long)(m0 + ldrow) * lda + k0 + ldc8);
        cp16(dst + 2 * TILE_B, Bh + (long)(n0 + ldrow) * ldb + k0 + ldc8);
        cp16(dst + 3 * TILE_B, Bl + (long)(n0 + ldrow) * ldb + k0 + ldc8);
    };

    issue(0); cp_commit();
    for (int it = 0; it < nch; it++) {
        if (it + 1 < nch) { issue(it + 1); cp_commit(); cp_wait1(); }
        else              { cp_wait0(); }
        __syncthreads();
        uint32_t base = sm32 + (it & 1) * STAGE_B;
        uint32_t aAddr = base + (aRow * HSTR + aK8) * 2;
        uint32_t bAddr = base + 2 * TILE_B + (bRow * HSTR + bK8) * 2;
#pragma unroll
        for (int ks = 0; ks < 2; ks++) {
            uint32_t ah[2][4], al[2][4], bh[4][2], bl[4][2];
#pragma unroll
            for (int mt = 0; mt < 2; mt++) {
                uint32_t a = aAddr + mt * (16 * HSTR * 2) + ks * 32;
                ldsm4(ah[mt][0], ah[mt][1], ah[mt][2], ah[mt][3], a);
                ldsm4(al[mt][0], al[mt][1], al[mt][2], al[mt][3], a + TILE_B);
            }
#pragma unroll
            for (int np = 0; np < 2; np++) {
                uint32_t b = bAddr + np * (16 * HSTR * 2) + ks * 32;
                ldsm4(bh[2 * np][0], bh[2 * np][1], bh[2 * np + 1][0], bh[2 * np + 1][1], b);
                ldsm4(bl[2 * np][0], bl[2 * np][1], bl[2 * np + 1][0], bl[2 * np + 1][1],
                      b + TILE_B);
            }
#pragma unroll
            for (int mt = 0; mt < 2; mt++)
#pragma unroll
                for (int nt = 0; nt < 4; nt++) {
                    mma_f16(c[mt][nt], ah[mt][0], ah[mt][1], ah[mt][2], ah[mt][3],
                            bh[nt][0], bh[nt][1]);
                    mma_f16(c[mt][nt], ah[mt][0], ah[mt][1], ah[mt][2], ah[mt][3],
                            bl[nt][0], bl[nt][1]);
                    mma_f16(c[mt][nt], al[mt][0], al[mt][1], al[mt][2], al[mt][3],
                            bh[nt][0], bh[nt][1]);
                }
        }
        __syncthreads();
    }

    // epilogue
#pragma unroll
    for (int mt = 0; mt < 2; mt++) {
        int gm = m0 + wm * 32 + mt * 16 + lr;
#pragma unroll
        for (int nt = 0; nt < 4; nt++) {
            int gn = n0 + wn * 32 + nt * 8 + 2 * lc;
#pragma unroll
            for (int half = 0; half < 2; half++) {
                int row = gm + half * 8;
                float v0 = c[mt][nt][2 * half + 0] * alpha;
                float v1 = c[mt][nt][2 * half + 1] * alpha;
                if (flags & 1) {
                    const float2 a = *(const float2*)(mask + (long)blockIdx.z * sMask +
                                                      (long)row * ldm + gn);
                    if (a.x == 0.0f) v0 += NEGV;
                    if (a.y == 0.0f) v1 += NEGV;
                }
                float2* dst = (float2*)(C + (long)row * ldc + gn);
                if (flags & 2) {
                    float2 o = *dst;
                    o.x += v0; o.y += v1;
                    *dst = o;
                } else {
                    *dst = make_float2(v0, v1);
                }
            }
        }
    }
}

// ---- pack weights -> hi/lo fp16 ----------------------------------------
__global__ void pack_w(const float* __restrict__ Wq, const float* __restrict__ Wk,
                       const float* __restrict__ Wqs, const float* __restrict__ Wv,
                       const float* __restrict__ Wqkv,
                       __half* __restrict__ Wh, __half* __restrict__ Wl) {
    int i = blockIdx.x * blockDim.x + threadIdx.x;
    if (i >= NPROJ * Cc) return;
    int row = i / Cc, col = i % Cc;
    float v;
    if      (row <  256) v = Wq  [ row         * Cc + col];
    else if (row <  512) v = Wk  [(row -  256) * Cc + col];
    else if (row <  768) v = Wqs [(row -  512) * Cc + col];
    else if (row < 1024) v = Wv  [(row -  768) * Cc + col];
    else                 v = Wqkv[(row - 1024) * Cc + col];
    split1(v, Wh + i, Wl + i);
}

// ---- x -> hi/lo fp16 ----------------------------------------------------
__global__ void conv_x(const float* __restrict__ x, __half* __restrict__ xh,
                       __half* __restrict__ xl) {
    int i = blockIdx.x * blockDim.x + threadIdx.x;
    if (i >= BT * Cc) return;
    split1(x[i], xh + i, xl + i);
}

// ---- idx from one-hot (warp per row) -----------------------------------
__global__ void extract_idx(const float* __restrict__ inxs, int* __restrict__ idx) {
    int w = (blockIdx.x * blockDim.x + threadIdx.x) >> 5;
    int lane = threadIdx.x & 31;
    if (w >= BT * Kk) return;
    const float4* p = (const float4*)(inxs + (long)w * Tt);
    int found = 0;
    for (int j = lane; j < Tt / 4; j += 32) {
        float4 v = p[j];
        if (v.x > 0.5f) found = 4 * j;
        if (v.y > 0.5f) found = 4 * j + 1;
        if (v.z > 0.5f) found = 4 * j + 2;
        if (v.w > 0.5f) found = 4 * j + 3;
    }
#pragma unroll
    for (int d = 16; d > 0; d >>= 1)
        found = max(found, __shfl_xor_sync(0xffffffffu, found, d));
    if (lane == 0) idx[w] = found;
}

// ---- normalize q,k,qs; emit hi/lo for q,mq,mk --------------------------
__global__ void prep_proj(float* __restrict__ proj, __half* __restrict__ qh,
                          __half* __restrict__ ql) {
    long row = blockIdx.x;
    int tid = threadIdx.x;
    __shared__ float red[8];
    __shared__ float bcast;
    for (int seg = 0; seg < 3; seg++) {
        long o = row * NPROJ + seg * 256 + tid;
        float v = proj[o];
        float ss = v * v;
#pragma unroll
        for (int d = 16; d > 0; d >>= 1) ss += __shfl_xor_sync(0xffffffffu, ss, d);
        if ((tid & 31) == 0) red[tid >> 5] = ss;
        __syncthreads();
        if (tid == 0) {
            float s = 0.f;
            for (int i = 0; i < 8; i++) s += red[i];
            bcast = 1.0f / fmaxf(sqrtf(s), 1e-12f);
        }
        __syncthreads();
        float nv = v * bcast;
        proj[o] = nv;
        if (seg == 0) split1(nv, qh + row * 768 + tid, ql + row * 768 + tid);
        __syncthreads();
    }
    float mq = proj[row * NPROJ + 1024 + tid];
    float mk = proj[row * NPROJ + 1280 + tid];
    split1(mq, qh + row * 768 + 256 + tid, ql + row * 768 + 256 + tid);
    split1(mk, qh + row * 768 + 512 + tid, ql + row * 768 + 512 + tid);
}

// ---- build [qs|kn_sum] and [qs|k] as hi/lo fp16 ------------------------
__global__ void build_ab(const float* __restrict__ proj, const int* __restrict__ idx,
                         __half* __restrict__ A2h, __half* __restrict__ A2l,
                         __half* __restrict__ B2h, __half* __restrict__ B2l,
                         const float* __restrict__ ns_w) {
    int row = blockIdx.x;
    int c = threadIdx.x;
    int b = row >> 9;
    long pbase = (long)row * NPROJ;
    float qs = proj[pbase + 512 + c];
    float kv = proj[pbase + 256 + c];
    long o = (long)row * 512;
    split1(qs, B2h + o + c, B2l + o + c);
    split1(kv, B2h + o + 256 + c, B2l + o + 256 + c);
    split1(qs, A2h + o + c, A2l + o + c);
    float s = 0.f;
#pragma unroll
    for (int n = 0; n < Kk; n++) {
        int t = idx[row * Kk + n];
        s += ns_w[n] * proj[((long)(b * Tt + t)) * NPROJ + 256 + c];
    }
    split1(s, A2h + o + 256 + c, A2l + o + 256 + c);
}

// ---- transpose v/mv into hi/lo [b][c][ v_t | mv_t ] --------------------
__global__ void transpose_v(const float* __restrict__ proj, __half* __restrict__ Vh,
                            __half* __restrict__ Vl) {
    __shared__ float tile[32][33];
    int which = blockIdx.z >> 3;
    int b = blockIdx.z & 7;
    int t0 = blockIdx.x * 32, c0 = blockIdx.y * 32;
    int tx = threadIdx.x & 31, ty = threadIdx.x >> 5;
    int srcCol = (which ? 1536 : 768) + c0;
    for (int i = ty; i < 32; i += 8)
        tile[i][tx] = proj[((long)(b * Tt + t0 + i)) * NPROJ + srcCol + tx];
    __syncthreads();
    long dbase = ((long)b * Cc + c0) * 1024 + which * 512 + t0;
    for (int i = ty; i < 32; i += 8)
        split1(tile[tx][i], Vh + dbase + (long)i * 1024 + tx,
               Vl + dbase + (long)i * 1024 + tx);
}

// ---- sim_nn gather/max (adds into L half of LD) ------------------------
__global__ void add_simnn(const float* __restrict__ Gq, const int* __restrict__ idx,
                          float* __restrict__ LD, const float* __restrict__ nn_w) {
    int i = blockIdx.x, b = blockIdx.y;
    int tid = threadIdx.x;
    __shared__ float srow[4][Tt];
    __shared__ int   sjdx[Tt * Kk];
    __shared__ float w[4];
    if (tid < 4) w[tid] = nn_w[tid];
    for (int j = tid; j < Tt * Kk; j += 256) sjdx[j] = idx[b * Tt * Kk + j];
#pragma unroll
    for (int x = 0; x < 4; x++) {
        int rx = idx[(b * Tt + i) * Kk + x];
        for (int c = tid; c < Tt; c += 256)
            srow[x][c] = Gq[((long)b * Tt + rx) * Tt + c];
    }
    __syncthreads();
    for (int j = tid; j < Tt; j += 256) {
        float acc = 0.f;
#pragma unroll
        for (int x = 0; x < 4; x++) {
            float m = -3.4e38f;
#pragma unroll
            for (int y = 0; y < 4; y++)
                m = fmaxf(m, srow[x][sjdx[j * Kk + y]]);
            acc += w[x] * m;
        }
        LD[((long)b * Tt + i) * 1024 + j] += acc;
    }
}

// ---- row softmax -> probs hi/lo fp16 -----------------------------------
__global__ void softmax_rows(const float* __restrict__ LD, __half* __restrict__ Ph,
                             __half* __restrict__ Pl) {
    long base = (long)blockIdx.x * 1024 + blockIdx.y * 512;
    const float* p = LD + base;
    int tid = threadIdx.x;
    __shared__ float red[8];
    __shared__ float bcast;
    float2 v = ((const float2*)p)[tid];
    float m = fmaxf(v.x, v.y);
#pragma unroll
    for (int d = 16; d > 0; d >>= 1) m = fmaxf(m, __shfl_xor_sync(0xffffffffu, m, d));
    if ((tid & 31) == 0) red[tid >> 5] = m;
    __syncthreads();
    if (tid == 0) {
        float mm = red[0];
        for (int i = 1; i < 8; i++) mm = fmaxf(mm, red[i]);
        bcast = mm;
    }
    __syncthreads();
    float mm = bcast;
    float e0 = __expf(v.x - mm), e1 = __expf(v.y - mm);
    float s = e0 + e1;
#pragma unroll
    for (int d = 16; d > 0; d >>= 1) s += __shfl_xor_sync(0xffffffffu, s, d);
    if ((tid & 31) == 0) red[tid >> 5] = s;
    __syncthreads();
    if (tid == 0) {
        float ss = 0.f;
        for (int i = 0; i < 8; i++) ss += red[i];
        bcast = 1.0f / ss;
    }
    __syncthreads();
    float inv = bcast;
    split1(e0 * inv, Ph + base + 2 * tid, Pl + base + 2 * tid);
    split1(e1 * inv, Ph + base + 2 * tid + 1, Pl + base + 2 * tid + 1);
}

// ---- host --------------------------------------------------------------
extern "C" void kernel_launch(void* const* d_in, const int* in_sizes, int n_in,
                              void* d_out, int out_size) {
    const float* x    = (const float*)d_in[0];
    const float* adj  = (const float*)d_in[1];
    const float* inxs = (const float*)d_in[2];
    const float* Wq   = (const float*)d_in[3];
    const float* Wk   = (const float*)d_in[4];
    const float* Wqs  = (const float*)d_in[5];
    const float* Wv   = (const float*)d_in[6];
    const float* nn_w = (const float*)d_in[7];
    const float* ns_w = (const float*)d_in[8];
    const float* Wqkv = (const float*)d_in[9];
    float* out = (float*)d_out;

    __half *pWh, *pWl, *pxh, *pxl, *pqh, *pql, *pA2h, *pA2l, *pB2h, *pB2l;
    __half *pPh, *pPl, *pVh, *pVl;
    float *pProj, *pGq, *pLD; int* pIdx;
    cudaGetSymbolAddress((void**)&pWh,  gh_Wall);
    cudaGetSymbolAddress((void**)&pWl,  gl_Wall);
    cudaGetSymbolAddress((void**)&pxh,  gh_x);
    cudaGetSymbolAddress((void**)&pxl,  gl_x);
    cudaGetSymbolAddress((void**)&pIdx, g_idx);
    cudaGetSymbolAddress((void**)&pProj, g_proj);
    cudaGetSymbolAddress((void**)&pqh,  gh_qmm);
    cudaGetSymbolAddress((void**)&pql,  gl_qmm);
    cudaGetSymbolAddress((void**)&pA2h, gh_A2);
    cudaGetSymbolAddress((void**)&pA2l, gl_A2);
    cudaGetSymbolAddress((void**)&pB2h, gh_B2);
    cudaGetSymbolAddress((void**)&pB2l, gl_B2);
    cudaGetSymbolAddress((void**)&pGq,  g_Gq);
    cudaGetSymbolAddress((void**)&pLD,  g_LD);
    cudaGetSymbolAddress((void**)&pPh,  gh_P);
    cudaGetSymbolAddress((void**)&pPl,  gl_P);
    cudaGetSymbolAddress((void**)&pVh,  gh_Vt);
    cudaGetSymbolAddress((void**)&pVl,  gl_Vt);

    cudaFuncSetAttribute(gemm_h, cudaFuncAttributeMaxDynamicSharedMemorySize, SMEM_DYN);

    const long sTT  = (long)Tt * Tt;
    const long sTQ  = (long)Tt * 768;
    const long sT5  = (long)Tt * 512;
    const long sTLD = (long)Tt * 1024;
    const long sTC  = (long)Tt * Cc;
    const long sVT  = (long)Cc * 1024;

    pack_w<<<(NPROJ * Cc + 255) / 256, 256>>>(Wq, Wk, Wqs, Wv, Wqkv, pWh, pWl);
    conv_x<<<(BT * Cc + 255) / 256, 256>>>(x, pxh, pxl);
    extract_idx<<<(BT * Kk * 32 + 255) / 256, 256>>>(inxs, pIdx);

    // proj = x @ Wall^T : (4096 x 1792), K=256
    gemm_h<<<dim3(NPROJ / 128, BT / 128, 1), 512, SMEM_DYN>>>(
        pxh, pxl, pWh, pWl, pProj, Cc, Cc, Cc, NPROJ, 0, 0, 0, 1.0f,
        nullptr, 0, 0, 0);

    transpose_v<<<dim3(Tt / 32, Cc / 32, 2 * Bb), 256>>>(pProj, pVh, pVl);
    prep_proj<<<BT, 256>>>(pProj, pqh, pql);
    build_ab<<<BT, 256>>>(pProj, pIdx, pA2h, pA2l, pB2h, pB2l, ns_w);

    // L half of LD = [qs|kn_sum] @ [qs|k]^T + mask : per-batch 512x512, K=512
    gemm_h<<<dim3(4, 4, Bb), 512, SMEM_DYN>>>(
        pA2h, pA2l, pB2h, pB2l, pLD, 512, 512, 512, 1024, sT5, sT5, sTLD, 1.0f,
        adj, sTT, Tt, 1);

    // Gq = q @ q^T : per-batch 512x512, K=256
    gemm_h<<<dim3(4, 4, Bb), 512, SMEM_DYN>>>(
        pqh, pql, pqh, pql, pGq, Cc, 768, 768, Tt, sTQ, sTQ, sTT, 1.0f,
        nullptr, 0, 0, 0);

    add_simnn<<<dim3(Tt, Bb), 256>>>(pGq, pIdx, pLD, nn_w);

    // D half of LD = mq @ mk^T * C^-0.5
    gemm_h<<<dim3(4, 4, Bb), 512, SMEM_DYN>>>(
        pqh + 256, pql + 256, pqh + 512, pql + 512, pLD + 512, Cc, 768, 768, 1024,
        sTQ, sTQ, sTLD, 0.0625f, nullptr, 0, 0, 0);

    softmax_rows<<<dim3(BT, 2), 256>>>(pLD, pPh, pPl);

    // out = [P_L | P_D] @ [v | mv]^T(K-major) : per-batch 512x256, K=1024
    gemm_h<<<dim3(Cc / 128, Tt / 128, Bb), 512, SMEM_DYN>>>(
        pPh, pPl, pVh, pVl, out, 1024, 1024, 1024, Cc, sTLD, sVT, sTC, 1.0f,
        nullptr, 0, 0, 0);
}

// round 8
// speedup vs baseline: 2.5185x; 1.1822x over previous
#include <cuda_runtime.h>
#include <cuda_fp16.h>
#include <cstdint>
#include <math.h>

#define Bb 8
#define Tt 512
#define Cc 256
#define Kk 4
constexpr int BT    = Bb * Tt;     // 4096
constexpr int NPROJ = 1792;        // [q|k|qs|v|mq|mk|mv]
constexpr float NEGV = -1e22f;

constexpr long sTT  = (long)Tt * Tt;
constexpr long sTQ  = (long)Tt * 768;
constexpr long sT5  = (long)Tt * 512;
constexpr long sTLD = (long)Tt * 1024;
constexpr long sTC  = (long)Tt * Cc;
constexpr long sVT  = (long)Cc * 1024;
constexpr long OUTN = (long)BT * Cc;          // 1M elements

// ---- scratch -----------------------------------------------------------
__device__ __half gh_Wall[NPROJ * Cc];
__device__ __half gl_Wall[NPROJ * Cc];
__device__ __half gh_x[BT * Cc];
__device__ __half gl_x[BT * Cc];
__device__ int    g_idx [BT * Kk];
__device__ float  g_proj[(long)BT * NPROJ];
__device__ __half gh_qmm[(long)BT * 768];   // [q|mq|mk]
__device__ __half gl_qmm[(long)BT * 768];
__device__ __half gh_A2[(long)BT * 512];
__device__ __half gl_A2[(long)BT * 512];
__device__ __half gh_B2[(long)BT * 512];
__device__ __half gl_B2[(long)BT * 512];
__device__ float  g_Gq [(long)Bb * Tt * Tt];
__device__ float  g_LD [(long)BT * 1024];   // logits [L|D]
__device__ __half gh_P [(long)BT * 1024];
__device__ __half gl_P [(long)BT * 1024];
__device__ __half gh_Vt[(long)Bb * Cc * 1024];
__device__ __half gl_Vt[(long)Bb * Cc * 1024];
__device__ float  g_part[4 * OUTN];         // split-K partials

// ---- PTX helpers -------------------------------------------------------
__device__ __forceinline__ uint32_t smem_u32(const void* p) {
    uint32_t a;
    asm("{ .reg .u64 t; cvta.to.shared.u64 t, %1; cvt.u32.u64 %0, t; }" : "=r"(a) : "l"(p));
    return a;
}
__device__ __forceinline__ void cp16(uint32_t s, const void* g) {
    asm volatile("cp.async.cg.shared.global [%0], [%1], 16;" :: "r"(s), "l"(g));
}
__device__ __forceinline__ void cp_commit() {
    asm volatile("cp.async.commit_group;" ::: "memory");
}
__device__ __forceinline__ void cp_wait1() {
    asm volatile("cp.async.wait_group 1;" ::: "memory");
}
__device__ __forceinline__ void ldsm4(uint32_t& r0, uint32_t& r1, uint32_t& r2,
                                      uint32_t& r3, uint32_t a) {
    asm volatile("ldmatrix.sync.aligned.m8n8.x4.shared.b16 {%0,%1,%2,%3}, [%4];"
                 : "=r"(r0), "=r"(r1), "=r"(r2), "=r"(r3) : "r"(a));
}
__device__ __forceinline__ void mma_f16(float* c, uint32_t a0, uint32_t a1, uint32_t a2,
                                        uint32_t a3, uint32_t b0, uint32_t b1) {
    asm volatile(
        "mma.sync.aligned.m16n8k16.row.col.f32.f16.f16.f32 "
        "{%0,%1,%2,%3}, {%4,%5,%6,%7}, {%8,%9}, {%0,%1,%2,%3};\n"
        : "+f"(c[0]), "+f"(c[1]), "+f"(c[2]), "+f"(c[3])
        : "r"(a0), "r"(a1), "r"(a2), "r"(a3), "r"(b0), "r"(b1));
}
__device__ __forceinline__ void split1(float v, __half* h, __half* l) {
    __half hh = __float2half_rn(v);
    *h = hh;
    *l = __float2half_rn(v - __half2float(hh));
}

// ---- fp16x3 tensor-core NT GEMM core (pre-split hi/lo inputs) ----------
// C[m,n] = alpha * sum_k A[m,k]*B[n,k]; flags: 1 = adj mask
constexpr int HSTR    = 40;                  // padded halves per smem row
constexpr int TILE_B  = 128 * HSTR * 2;      // 10240 B
constexpr int STAGE_B = 4 * TILE_B;          // 40960 B
constexpr int NSTAGE  = 3;
constexpr int SMEM_DYN = NSTAGE * STAGE_B;   // 122880 B

__device__ __forceinline__ void gemm_core(
    const __half* __restrict__ Ah, const __half* __restrict__ Al,
    const __half* __restrict__ Bh, const __half* __restrict__ Bl,
    float* __restrict__ C, int nch, int lda, int ldb, int ldc, float alpha,
    const float* __restrict__ mask, int ldm, int flags, int m0, int n0, char* sm) {
    uint32_t sm32 = smem_u32(sm);
    int tid = threadIdx.x;
    int wid = tid >> 5, lane = tid & 31;
    int wm = wid >> 2, wn = wid & 3;             // 4x4 warp grid, 32x32 tiles
    int lr = lane >> 2, lc = lane & 3;

    int ldrow = tid >> 2;                        // 0..127
    int ldc8  = (tid & 3) * 8;

    int aRow = wm * 32 + (lane & 15);
    int aK8  = (lane >> 4) * 8;
    int quad = lane >> 3, rb = lane & 7;
    int bRow = wn * 32 + (quad >> 1) * 8 + rb;
    int bK8  = (quad & 1) * 8;

    float c[2][4][4];
#pragma unroll
    for (int i = 0; i < 2; i++)
#pragma unroll
        for (int j = 0; j < 4; j++)
#pragma unroll
            for (int e = 0; e < 4; e++) c[i][j][e] = 0.f;

    auto issue = [&](int it) {
        uint32_t base = sm32 + (it % NSTAGE) * STAGE_B;
        int k0 = it * 32;
        uint32_t dst = base + (ldrow * HSTR + ldc8) * 2;
        cp16(dst,              Ah + (long)(m0 + ldrow) * lda + k0 + ldc8);
        cp16(dst + TILE_B,     Al + (long)(m0 + ldrow) * lda + k0 + ldc8);
        cp16(dst + 2 * TILE_B, Bh + (long)(n0 + ldrow) * ldb + k0 + ldc8);
        cp16(dst + 3 * TILE_B, Bl + (long)(n0 + ldrow) * ldb + k0 + ldc8);
    };

    issue(0); cp_commit();
    issue(1); cp_commit();
    for (int it = 0; it < nch; it++) {
        cp_wait1();                 // stage it resident (newest group may pend)
        __syncthreads();            // all warps done reading buffer (it-1)%3
        if (it + 2 < nch) issue(it + 2);
        cp_commit();
        uint32_t base = sm32 + (it % NSTAGE) * STAGE_B;
        uint32_t aAddr = base + (aRow * HSTR + aK8) * 2;
        uint32_t bAddr = base + 2 * TILE_B + (bRow * HSTR + bK8) * 2;
#pragma unroll
        for (int ks = 0; ks < 2; ks++) {
            uint32_t ah[2][4], al[2][4], bh[4][2], bl[4][2];
#pragma unroll
            for (int mt = 0; mt < 2; mt++) {
                uint32_t a = aAddr + mt * (16 * HSTR * 2) + ks * 32;
                ldsm4(ah[mt][0], ah[mt][1], ah[mt][2], ah[mt][3], a);
                ldsm4(al[mt][0], al[mt][1], al[mt][2], al[mt][3], a + TILE_B);
            }
#pragma unroll
            for (int np = 0; np < 2; np++) {
                uint32_t b = bAddr + np * (16 * HSTR * 2) + ks * 32;
                ldsm4(bh[2 * np][0], bh[2 * np][1], bh[2 * np + 1][0], bh[2 * np + 1][1], b);
                ldsm4(bl[2 * np][0], bl[2 * np][1], bl[2 * np + 1][0], bl[2 * np + 1][1],
                      b + TILE_B);
            }
#pragma unroll
            for (int mt = 0; mt < 2; mt++)
#pragma unroll
                for (int nt = 0; nt < 4; nt++) {
                    mma_f16(c[mt][nt], ah[mt][0], ah[mt][1], ah[mt][2], ah[mt][3],
                            bh[nt][0], bh[nt][1]);
                    mma_f16(c[mt][nt], ah[mt][0], ah[mt][1], ah[mt][2], ah[mt][3],
                            bl[nt][0], bl[nt][1]);
                    mma_f16(c[mt][nt], al[mt][0], al[mt][1], al[mt][2], al[mt][3],
                            bh[nt][0], bh[nt][1]);
                }
        }
    }

    // epilogue
#pragma unroll
    for (int mt = 0; mt < 2; mt++) {
        int gm = m0 + wm * 32 + mt * 16 + lr;
#pragma unroll
        for (int nt = 0; nt < 4; nt++) {
            int gn = n0 + wn * 32 + nt * 8 + 2 * lc;
#pragma unroll
            for (int half = 0; half < 2; half++) {
                int row = gm + half * 8;
                float v0 = c[mt][nt][2 * half + 0] * alpha;
                float v1 = c[mt][nt][2 * half + 1] * alpha;
                if (flags & 1) {
                    const float2 a = *(const float2*)(mask + (long)row * ldm + gn);
                    if (a.x == 0.0f) v0 += NEGV;
                    if (a.y == 0.0f) v1 += NEGV;
                }
                *(float2*)(C + (long)row * ldc + gn) = make_float2(v0, v1);
            }
        }
    }
}

// ---- proj GEMM: x @ Wall^T --------------------------------------------
__global__ void __launch_bounds__(512)
gemm_proj() {
    extern __shared__ char sm[];
    gemm_core(gh_x, gl_x, gh_Wall, gl_Wall, g_proj, Cc / 32, Cc, Cc, NPROJ,
              1.0f, nullptr, 0, 0, blockIdx.y * 128, blockIdx.x * 128, sm);
}

// ---- mid GEMMs merged: job0=L(+mask) job1=Gq job2=D --------------------
__global__ void __launch_bounds__(512)
gemm_mid(const float* __restrict__ adj) {
    extern __shared__ char sm[];
    int job = blockIdx.z >> 3, b = blockIdx.z & 7;
    int m0 = blockIdx.y * 128, n0 = blockIdx.x * 128;
    if (job == 0) {
        gemm_core(gh_A2 + b * sT5, gl_A2 + b * sT5, gh_B2 + b * sT5, gl_B2 + b * sT5,
                  g_LD + b * sTLD, 16, 512, 512, 1024, 1.0f,
                  adj + b * sTT, Tt, 1, m0, n0, sm);
    } else if (job == 1) {
        gemm_core(gh_qmm + b * sTQ, gl_qmm + b * sTQ, gh_qmm + b * sTQ, gl_qmm + b * sTQ,
                  g_Gq + b * sTT, 8, 768, 768, 512, 1.0f,
                  nullptr, 0, 0, m0, n0, sm);
    } else {
        gemm_core(gh_qmm + b * sTQ + 256, gl_qmm + b * sTQ + 256,
                  gh_qmm + b * sTQ + 512, gl_qmm + b * sTQ + 512,
                  g_LD + b * sTLD + 512, 8, 768, 768, 1024, 0.0625f,
                  nullptr, 0, 0, m0, n0, sm);
    }
}

// ---- output GEMM split-K: slice s covers k in [s*256, s*256+256) -------
__global__ void __launch_bounds__(512)
gemm_out() {
    extern __shared__ char sm[];
    int s = blockIdx.z >> 3, b = blockIdx.z & 7;
    gemm_core(gh_P + b * sTLD + s * 256, gl_P + b * sTLD + s * 256,
              gh_Vt + b * sVT + s * 256, gl_Vt + b * sVT + s * 256,
              g_part + (long)s * OUTN + b * sTC, 8, 1024, 1024, Cc, 1.0f,
              nullptr, 0, 0, blockIdx.y * 128, blockIdx.x * 128, sm);
}

// ---- reduce 4 partials into out (deterministic order) ------------------
__global__ void reduce_out(float* __restrict__ out) {
    long i = (long)(blockIdx.x * blockDim.x + threadIdx.x) * 4;
    if (i >= OUTN) return;
    const float4 p0 = *(const float4*)(g_part + i);
    const float4 p1 = *(const float4*)(g_part + OUTN + i);
    const float4 p2 = *(const float4*)(g_part + 2 * OUTN + i);
    const float4 p3 = *(const float4*)(g_part + 3 * OUTN + i);
    *(float4*)(out + i) = make_float4((p0.x + p1.x) + (p2.x + p3.x),
                                      (p0.y + p1.y) + (p2.y + p3.y),
                                      (p0.z + p1.z) + (p2.z + p3.z),
                                      (p0.w + p1.w) + (p2.w + p3.w));
}

// ---- pack weights -> hi/lo fp16 ----------------------------------------
__global__ void pack_w(const float* __restrict__ Wq, const float* __restrict__ Wk,
                       const float* __restrict__ Wqs, const float* __restrict__ Wv,
                       const float* __restrict__ Wqkv,
                       __half* __restrict__ Wh, __half* __restrict__ Wl) {
    int i = blockIdx.x * blockDim.x + threadIdx.x;
    if (i >= NPROJ * Cc) return;
    int row = i / Cc, col = i % Cc;
    float v;
    if      (row <  256) v = Wq  [ row         * Cc + col];
    else if (row <  512) v = Wk  [(row -  256) * Cc + col];
    else if (row <  768) v = Wqs [(row -  512) * Cc + col];
    else if (row < 1024) v = Wv  [(row -  768) * Cc + col];
    else                 v = Wqkv[(row - 1024) * Cc + col];
    split1(v, Wh + i, Wl + i);
}

// ---- x -> hi/lo fp16 ----------------------------------------------------
__global__ void conv_x(const float* __restrict__ x, __half* __restrict__ xh,
                       __half* __restrict__ xl) {
    int i = blockIdx.x * blockDim.x + threadIdx.x;
    if (i >= BT * Cc) return;
    split1(x[i], xh + i, xl + i);
}

// ---- idx from one-hot (warp per row) -----------------------------------
__global__ void extract_idx(const float* __restrict__ inxs, int* __restrict__ idx) {
    int w = (blockIdx.x * blockDim.x + threadIdx.x) >> 5;
    int lane = threadIdx.x & 31;
    if (w >= BT * Kk) return;
    const float4* p = (const float4*)(inxs + (long)w * Tt);
    int found = 0;
    for (int j = lane; j < Tt / 4; j += 32) {
        float4 v = p[j];
        if (v.x > 0.5f) found = 4 * j;
        if (v.y > 0.5f) found = 4 * j + 1;
        if (v.z > 0.5f) found = 4 * j + 2;
        if (v.w > 0.5f) found = 4 * j + 3;
    }
#pragma unroll
    for (int d = 16; d > 0; d >>= 1)
        found = max(found, __shfl_xor_sync(0xffffffffu, found, d));
    if (lane == 0) idx[w] = found;
}

// ---- normalize q,k,qs; emit hi/lo for q,mq,mk --------------------------
__global__ void prep_proj(float* __restrict__ proj, __half* __restrict__ qh,
                          __half* __restrict__ ql) {
    long row = blockIdx.x;
    int tid = threadIdx.x;
    __shared__ float red[8];
    __shared__ float bcast;
    for (int seg = 0; seg < 3; seg++) {
        long o = row * NPROJ + seg * 256 + tid;
        float v = proj[o];
        float ss = v * v;
#pragma unroll
        for (int d = 16; d > 0; d >>= 1) ss += __shfl_xor_sync(0xffffffffu, ss, d);
        if ((tid & 31) == 0) red[tid >> 5] = ss;
        __syncthreads();
        if (tid == 0) {
            float s = 0.f;
            for (int i = 0; i < 8; i++) s += red[i];
            bcast = 1.0f / fmaxf(sqrtf(s), 1e-12f);
        }
        __syncthreads();
        float nv = v * bcast;
        proj[o] = nv;
        if (seg == 0) split1(nv, qh + row * 768 + tid, ql + row * 768 + tid);
        __syncthreads();
    }
    float mq = proj[row * NPROJ + 1024 + tid];
    float mk = proj[row * NPROJ + 1280 + tid];
    split1(mq, qh + row * 768 + 256 + tid, ql + row * 768 + 256 + tid);
    split1(mk, qh + row * 768 + 512 + tid, ql + row * 768 + 512 + tid);
}

// ---- build [qs|kn_sum] and [qs|k] as hi/lo fp16 ------------------------
__global__ void build_ab(const float* __restrict__ proj, const int* __restrict__ idx,
                         __half* __restrict__ A2h, __half* __restrict__ A2l,
                         __half* __restrict__ B2h, __half* __restrict__ B2l,
                         const float* __restrict__ ns_w) {
    int row = blockIdx.x;
    int c = threadIdx.x;
    int b = row >> 9;
    long pbase = (long)row * NPROJ;
    float qs = proj[pbase + 512 + c];
    float kv = proj[pbase + 256 + c];
    long o = (long)row * 512;
    split1(qs, B2h + o + c, B2l + o + c);
    split1(kv, B2h + o + 256 + c, B2l + o + 256 + c);
    split1(qs, A2h + o + c, A2l + o + c);
    float s = 0.f;
#pragma unroll
    for (int n = 0; n < Kk; n++) {
        int t = idx[row * Kk + n];
        s += ns_w[n] * proj[((long)(b * Tt + t)) * NPROJ + 256 + c];
    }
    split1(s, A2h + o + 256 + c, A2l + o + 256 + c);
}

// ---- transpose v/mv into hi/lo [b][c][ v_t | mv_t ] --------------------
__global__ void transpose_v(const float* __restrict__ proj, __half* __restrict__ Vh,
                            __half* __restrict__ Vl) {
    __shared__ float tile[32][33];
    int which = blockIdx.z >> 3;
    int b = blockIdx.z & 7;
    int t0 = blockIdx.x * 32, c0 = blockIdx.y * 32;
    int tx = threadIdx.x & 31, ty = threadIdx.x >> 5;
    int srcCol = (which ? 1536 : 768) + c0;
    for (int i = ty; i < 32; i += 8)
        tile[i][tx] = proj[((long)(b * Tt + t0 + i)) * NPROJ + srcCol + tx];
    __syncthreads();
    long dbase = ((long)b * Cc + c0) * 1024 + which * 512 + t0;
    for (int i = ty; i < 32; i += 8)
        split1(tile[tx][i], Vh + dbase + (long)i * 1024 + tx,
               Vl + dbase + (long)i * 1024 + tx);
}

// ---- sim_nn gather/max (adds into L half of LD) ------------------------
__global__ void add_simnn(const float* __restrict__ Gq, const int* __restrict__ idx,
                          float* __restrict__ LD, const float* __restrict__ nn_w) {
    int i = blockIdx.x, b = blockIdx.y;
    int tid = threadIdx.x;
    __shared__ float srow[4][Tt];
    __shared__ int   sjdx[Tt * Kk];
    __shared__ float w[4];
    if (tid < 4) w[tid] = nn_w[tid];
    for (int j = tid; j < Tt * Kk; j += 256) sjdx[j] = idx[b * Tt * Kk + j];
#pragma unroll
    for (int x = 0; x < 4; x++) {
        int rx = idx[(b * Tt + i) * Kk + x];
        for (int c = tid; c < Tt; c += 256)
            srow[x][c] = Gq[((long)b * Tt + rx) * Tt + c];
    }
    __syncthreads();
    for (int j = tid; j < Tt; j += 256) {
        float acc = 0.f;
#pragma unroll
        for (int x = 0; x < 4; x++) {
            float m = -3.4e38f;
#pragma unroll
            for (int y = 0; y < 4; y++)
                m = fmaxf(m, srow[x][sjdx[j * Kk + y]]);
            acc += w[x] * m;
        }
        LD[((long)b * Tt + i) * 1024 + j] += acc;
    }
}

// ---- row softmax -> probs hi/lo fp16 -----------------------------------
__global__ void softmax_rows(const float* __restrict__ LD, __half* __restrict__ Ph,
                             __half* __restrict__ Pl) {
    long base = (long)blockIdx.x * 1024 + blockIdx.y * 512;
    const float* p = LD + base;
    int tid = threadIdx.x;
    __shared__ float red[8];
    __shared__ float bcast;
    float2 v = ((const float2*)p)[tid];
    float m = fmaxf(v.x, v.y);
#pragma unroll
    for (int d = 16; d > 0; d >>= 1) m = fmaxf(m, __shfl_xor_sync(0xffffffffu, m, d));
    if ((tid & 31) == 0) red[tid >> 5] = m;
    __syncthreads();
    if (tid == 0) {
        float mm = red[0];
        for (int i = 1; i < 8; i++) mm = fmaxf(mm, red[i]);
        bcast = mm;
    }
    __syncthreads();
    float mm = bcast;
    float e0 = __expf(v.x - mm), e1 = __expf(v.y - mm);
    float s = e0 + e1;
#pragma unroll
    for (int d = 16; d > 0; d >>= 1) s += __shfl_xor_sync(0xffffffffu, s, d);
    if ((tid & 31) == 0) red[tid >> 5] = s;
    __syncthreads();
    if (tid == 0) {
        float ss = 0.f;
        for (int i = 0; i < 8; i++) ss += red[i];
        bcast = 1.0f / ss;
    }
    __syncthreads();
    float inv = bcast;
    split1(e0 * inv, Ph + base + 2 * tid, Pl + base + 2 * tid);
    split1(e1 * inv, Ph + base + 2 * tid + 1, Pl + base + 2 * tid + 1);
}

// ---- host --------------------------------------------------------------
extern "C" void kernel_launch(void* const* d_in, const int* in_sizes, int n_in,
                              void* d_out, int out_size) {
    const float* x    = (const float*)d_in[0];
    const float* adj  = (const float*)d_in[1];
    const float* inxs = (const float*)d_in[2];
    const float* Wq   = (const float*)d_in[3];
    const float* Wk   = (const float*)d_in[4];
    const float* Wqs  = (const float*)d_in[5];
    const float* Wv   = (const float*)d_in[6];
    const float* nn_w = (const float*)d_in[7];
    const float* ns_w = (const float*)d_in[8];
    const float* Wqkv = (const float*)d_in[9];
    float* out = (float*)d_out;

    __half *pWh, *pWl, *pxh, *pxl, *pqh, *pql, *pA2h, *pA2l, *pB2h, *pB2l;
    __half *pPh, *pPl, *pVh, *pVl;
    float *pProj, *pGq, *pLD; int* pIdx;
    cudaGetSymbolAddress((void**)&pWh,  gh_Wall);
    cudaGetSymbolAddress((void**)&pWl,  gl_Wall);
    cudaGetSymbolAddress((void**)&pxh,  gh_x);
    cudaGetSymbolAddress((void**)&pxl,  gl_x);
    cudaGetSymbolAddress((void**)&pIdx, g_idx);
    cudaGetSymbolAddress((void**)&pProj, g_proj);
    cudaGetSymbolAddress((void**)&pqh,  gh_qmm);
    cudaGetSymbolAddress((void**)&pql,  gl_qmm);
    cudaGetSymbolAddress((void**)&pA2h, gh_A2);
    cudaGetSymbolAddress((void**)&pA2l, gl_A2);
    cudaGetSymbolAddress((void**)&pB2h, gh_B2);
    cudaGetSymbolAddress((void**)&pB2l, gl_B2);
    cudaGetSymbolAddress((void**)&pGq,  g_Gq);
    cudaGetSymbolAddress((void**)&pLD,  g_LD);
    cudaGetSymbolAddress((void**)&pPh,  gh_P);
    cudaGetSymbolAddress((void**)&pPl,  gl_P);
    cudaGetSymbolAddress((void**)&pVh,  gh_Vt);
    cudaGetSymbolAddress((void**)&pVl,  gl_Vt);

    cudaFuncSetAttribute(gemm_proj, cudaFuncAttributeMaxDynamicSharedMemorySize, SMEM_DYN);
    cudaFuncSetAttribute(gemm_mid,  cudaFuncAttributeMaxDynamicSharedMemorySize, SMEM_DYN);
    cudaFuncSetAttribute(gemm_out,  cudaFuncAttributeMaxDynamicSharedMemorySize, SMEM_DYN);

    pack_w<<<(NPROJ * Cc + 255) / 256, 256>>>(Wq, Wk, Wqs, Wv, Wqkv, pWh, pWl);
    conv_x<<<(BT * Cc + 255) / 256, 256>>>(x, pxh, pxl);
    extract_idx<<<(BT * Kk * 32 + 255) / 256, 256>>>(inxs, pIdx);

    // proj = x @ Wall^T : (4096 x 1792), K=256
    gemm_proj<<<dim3(NPROJ / 128, BT / 128, 1), 512, SMEM_DYN>>>();

    transpose_v<<<dim3(Tt / 32, Cc / 32, 2 * Bb), 256>>>(pProj, pVh, pVl);
    prep_proj<<<BT, 256>>>(pProj, pqh, pql);
    build_ab<<<BT, 256>>>(pProj, pIdx, pA2h, pA2l, pB2h, pB2l, ns_w);

    // merged: L(+mask), Gq, D  — grid 4x4x24
    gemm_mid<<<dim3(4, 4, 24), 512, SMEM_DYN>>>(adj);

    add_simnn<<<dim3(Tt, Bb), 256>>>(pGq, pIdx, pLD, nn_w);
    softmax_rows<<<dim3(BT, 2), 256>>>(pLD, pPh, pPl);

    // out: split-K=4 partials then reduce
    gemm_out<<<dim3(Cc / 128, Tt / 128, 32), 512, SMEM_DYN>>>();
    reduce_out<<<(int)(OUTN / 4 + 255) / 256, 256>>>(out);
}